// round 5
// baseline (speedup 1.0000x reference)
#include <cuda_runtime.h>
#include <cstdint>
#include <math.h>

// ---------------- problem constants ----------------
#define NL   2
#define DDIM 1024
#define HH   16
#define HDIM 64
#define FFD  4096
#define SS   1024
#define NB   2
#define LLQ  4096
#define ROWS_T (LLQ*NB)   // 8192 query rows
#define ROWS_S (SS*NB)    // 2048 kv rows
#define SCALING 0.125f    // HD^-0.5

// ---------------- device scratch (static, allocation-free) ----------------
__device__ float g_q   [ROWS_T*DDIM];
__device__ float g_k   [ROWS_S*DDIM];
__device__ float g_v   [ROWS_S*DDIM];
__device__ float g_w   [134217728];      // NB*HH*LLQ*SS attention weights (512MB)
__device__ float g_wpad[NB*HH*LLQ];
__device__ float g_attn[ROWS_T*DDIM];
__device__ float g_x1  [ROWS_T*DDIM];
__device__ float g_x   [ROWS_T*DDIM];
__device__ float g_h   [ROWS_T*FFD];
__device__ float g_y   [ROWS_T*DDIM];
__device__ float g_tgt [ROWS_T*DDIM];
__device__ float g_noise[NL*NB*HH*HDIM];

// ---------------- JAX threefry2x32 reproduction ----------------
__device__ __forceinline__ uint32_t rotl32(uint32_t x, int d) {
    return (x << d) | (x >> (32 - d));
}
__device__ __forceinline__ void threefry2x32(uint32_t k0, uint32_t k1,
                                             uint32_t& x0, uint32_t& x1) {
    uint32_t ks2 = k0 ^ k1 ^ 0x1BD11BDAu;
    x0 += k0; x1 += k1;
#define TFR(r) { x0 += x1; x1 = rotl32(x1, (r)); x1 ^= x0; }
    TFR(13) TFR(15) TFR(26) TFR(6)
    x0 += k1; x1 += ks2 + 1u;
    TFR(17) TFR(29) TFR(16) TFR(24)
    x0 += ks2; x1 += k0 + 2u;
    TFR(13) TFR(15) TFR(26) TFR(6)
    x0 += k0; x1 += k1 + 3u;
    TFR(17) TFR(29) TFR(16) TFR(24)
    x0 += k1; x1 += ks2 + 4u;
    TFR(13) TFR(15) TFR(26) TFR(6)
    x0 += ks2; x1 += k0 + 5u;
#undef TFR
}
__device__ __forceinline__ float bits_to_normal(uint32_t b) {
    // jax uniform(-1+eps, 1) then sqrt(2)*erfinv
    float f = __uint_as_float((b >> 9) | 0x3F800000u) - 1.0f;   // [0,1)
    const float lo = -0.99999994f;                               // nextafter(-1,0)
    float u = fmaxf(lo, f * 2.0f + lo);                          // (hi-lo) rounds to 2.0f
    return 1.4142135623730951f * erfinvf(u);
}
// Partitionable threefry (JAX default since 0.4.36):
// bits[j] = y0 ^ y1 where (y0,y1) = threefry2x32(key, (j>>32, j&0xffffffff)).
// noise[layer][ (n*H+h)*HD + d ], 2048 values per layer.
__global__ void noise_kernel(float* __restrict__ noise) {
    int j = blockIdx.x * blockDim.x + threadIdx.x;
    if (j >= NL * 2048) return;
    int layer = j / 2048, jj = j % 2048;
    // fold_in(key(42), layer): threefry(key=(0,42), count=(0,layer))
    uint32_t k0 = 0u, k1 = 42u, x0 = 0u, x1 = (uint32_t)layer;
    threefry2x32(k0, k1, x0, x1);
    // counter-based bits: counts_hi = 0 (jj < 2^32), counts_lo = jj
    uint32_t b0 = 0u, b1 = (uint32_t)jj;
    threefry2x32(x0, x1, b0, b1);
    noise[layer * 2048 + jj] = bits_to_normal(b0 ^ b1);
}

// ---------------- generic tiled fp32 GEMM ----------------
// C[m,n] = epi( alpha*(sum_k A[m,k]*B(k,n) + bias[n]) + resid[m,n] )
// TRANSB: B is (N,K) row-major (B(k,n)=B[n*ldb+k]); else B is (K,N) (B(k,n)=B[k*ldb+n])
template<int BM, int BN, int BK, int TM, int TN, bool TRANSB>
__global__ __launch_bounds__((BM/TM)*(BN/TN))
void gemm_kernel(int M, int Nn, int K,
                 const float* __restrict__ A, int lda, long long sA,
                 const float* __restrict__ B, int ldb, long long sB,
                 const float* __restrict__ bias, float alpha,
                 const float* __restrict__ resid, int ldr, int relu,
                 float* __restrict__ C, int ldc, long long sC)
{
    constexpr int TX = BN / TN, TY = BM / TM, NT = TX * TY;
    __shared__ float As[BK][BM];
    __shared__ float Bs[BK][BN];

    long long bz = blockIdx.z;
    A += bz * sA; B += bz * sB; C += bz * sC;
    const int bm = blockIdx.y * BM;
    const int bn = blockIdx.x * BN;
    const int tid = threadIdx.x;
    const int tx = tid % TX, ty = tid / TX;

    float acc[TM][TN];
#pragma unroll
    for (int i = 0; i < TM; i++)
#pragma unroll
        for (int j = 0; j < TN; j++) acc[i][j] = 0.f;

    for (int k0 = 0; k0 < K; k0 += BK) {
        // load A tile (BM x BK), transpose into As[k][m]
        {
            constexpr int NV = BM * BK / 4;
#pragma unroll
            for (int vi = tid; vi < NV; vi += NT) {
                int r  = vi / (BK / 4);
                int kc = (vi % (BK / 4)) * 4;
                float4 t = *reinterpret_cast<const float4*>(
                    A + (long long)(bm + r) * lda + k0 + kc);
                As[kc + 0][r] = t.x; As[kc + 1][r] = t.y;
                As[kc + 2][r] = t.z; As[kc + 3][r] = t.w;
            }
        }
        if (TRANSB) {
            constexpr int NV = BN * BK / 4;
#pragma unroll
            for (int vi = tid; vi < NV; vi += NT) {
                int r  = vi / (BK / 4);
                int kc = (vi % (BK / 4)) * 4;
                float4 t = *reinterpret_cast<const float4*>(
                    B + (long long)(bn + r) * ldb + k0 + kc);
                Bs[kc + 0][r] = t.x; Bs[kc + 1][r] = t.y;
                Bs[kc + 2][r] = t.z; Bs[kc + 3][r] = t.w;
            }
        } else {
            constexpr int NV = BK * BN / 4;
#pragma unroll
            for (int vi = tid; vi < NV; vi += NT) {
                int kk = vi / (BN / 4);
                int c  = (vi % (BN / 4)) * 4;
                float4 t = *reinterpret_cast<const float4*>(
                    B + (long long)(k0 + kk) * ldb + bn + c);
                *reinterpret_cast<float4*>(&Bs[kk][c]) = t;
            }
        }
        __syncthreads();

#pragma unroll
        for (int kk = 0; kk < BK; kk++) {
            float ra[TM], rb[TN];
#pragma unroll
            for (int i = 0; i < TM; i += 4)
                *reinterpret_cast<float4*>(&ra[i]) =
                    *reinterpret_cast<const float4*>(&As[kk][ty * TM + i]);
#pragma unroll
            for (int j = 0; j < TN; j += 4)
                *reinterpret_cast<float4*>(&rb[j]) =
                    *reinterpret_cast<const float4*>(&Bs[kk][tx * TN + j]);
#pragma unroll
            for (int i = 0; i < TM; i++)
#pragma unroll
                for (int j = 0; j < TN; j++)
                    acc[i][j] += ra[i] * rb[j];
        }
        __syncthreads();
    }

#pragma unroll
    for (int i = 0; i < TM; i++) {
        long long r = bm + ty * TM + i;
#pragma unroll
        for (int j = 0; j < TN; j++) {
            int c = bn + tx * TN + j;
            float vv = acc[i][j];
            if (bias)  vv += bias[c];
            vv *= alpha;
            if (resid) vv += resid[r * (long long)ldr + c];
            if (relu)  vv = fmaxf(vv, 0.f);
            C[r * (long long)ldc + c] = vv;
        }
    }
}

// ---------------- softmax over S=1024 (+ implicit zero pad column) ----------------
__global__ void softmax_kernel(float* __restrict__ w, float* __restrict__ wpad) {
    long long row = blockIdx.x;
    float4* p = reinterpret_cast<float4*>(w + row * (long long)SS);
    int t = threadIdx.x;                 // 256 threads, 4 elems each
    float4 v = p[t];
    __shared__ float red[256];
    float m = fmaxf(fmaxf(v.x, v.y), fmaxf(v.z, v.w));
    red[t] = m; __syncthreads();
    for (int o = 128; o > 0; o >>= 1) {
        if (t < o) red[t] = fmaxf(red[t], red[t + o]);
        __syncthreads();
    }
    m = fmaxf(red[0], 0.f);              // pad score = 0
    __syncthreads();
    v.x = expf(v.x - m); v.y = expf(v.y - m);
    v.z = expf(v.z - m); v.w = expf(v.w - m);
    red[t] = v.x + v.y + v.z + v.w; __syncthreads();
    for (int o = 128; o > 0; o >>= 1) {
        if (t < o) red[t] += red[t + o];
        __syncthreads();
    }
    float epad = expf(-m);
    float inv = 1.f / (red[0] + epad);
    v.x *= inv; v.y *= inv; v.z *= inv; v.w *= inv;
    p[t] = v;
    if (t == 0) wpad[row] = epad * inv;
}

// ---------------- layernorm over D=1024 ----------------
__global__ void ln_kernel(const float* __restrict__ x, const float* __restrict__ g,
                          const float* __restrict__ b, float* __restrict__ y) {
    long long row = blockIdx.x;
    const float4* px = reinterpret_cast<const float4*>(x + row * (long long)DDIM);
    int t = threadIdx.x;
    float4 v = px[t];
    __shared__ float r1[256], r2[256];
    r1[t] = v.x + v.y + v.z + v.w;
    r2[t] = v.x*v.x + v.y*v.y + v.z*v.z + v.w*v.w;
    __syncthreads();
    for (int o = 128; o > 0; o >>= 1) {
        if (t < o) { r1[t] += r1[t + o]; r2[t] += r2[t + o]; }
        __syncthreads();
    }
    float mu  = r1[0] * (1.f / DDIM);
    float var = r2[0] * (1.f / DDIM) - mu * mu;
    float rs  = rsqrtf(var + 1e-5f);
    float4 gg = reinterpret_cast<const float4*>(g)[t];
    float4 bb = reinterpret_cast<const float4*>(b)[t];
    float4 o4;
    o4.x = (v.x - mu) * rs * gg.x + bb.x;
    o4.y = (v.y - mu) * rs * gg.y + bb.y;
    o4.z = (v.z - mu) * rs * gg.z + bb.z;
    o4.w = (v.w - mu) * rs * gg.w + bb.w;
    reinterpret_cast<float4*>(y + row * (long long)DDIM)[t] = o4;
}

// ---------------- attn_map = mean_h sigmoid(w) ----------------
__global__ void attnmap_kernel(const float* __restrict__ w, float* __restrict__ out) {
    long long idx = (long long)blockIdx.x * blockDim.x + threadIdx.x;
    if (idx >= (long long)NB * LLQ * SS) return;
    int s = (int)(idx & (SS - 1));
    long long t2 = idx >> 10;
    int l = (int)(t2 & (LLQ - 1));
    int n = (int)(t2 >> 12);
    float acc = 0.f;
#pragma unroll
    for (int h = 0; h < HH; h++) {
        float v = w[(((long long)(n * HH + h) * LLQ + l) << 10) + s];
        acc += 1.f / (1.f + expf(-v));
    }
    out[idx] = acc * (1.f / HH);
}

// ---------------- add pad-column noise contribution ----------------
__global__ void addnoise_kernel(float* __restrict__ attn,
                                const float* __restrict__ wpad,
                                const float* __restrict__ noise) {
    long long idx = (long long)blockIdx.x * blockDim.x + threadIdx.x;
    if (idx >= (long long)ROWS_T * DDIM) return;
    int c = (int)(idx & 1023);
    long long r = idx >> 10;          // r = l*NB + n
    int n = (int)(r & 1);
    int l = (int)(r >> 1);
    int h = c >> 6, d = c & 63;
    attn[idx] += wpad[(n * HH + h) * LLQ + l] * noise[(n * HH + h) * HDIM + d];
}

// ---------------- host launchers ----------------
static void gemm_tb(int M, int Nn, int K,
                    const float* A, int lda, long long sA,
                    const float* B, int ldb, long long sB,
                    const float* bias, float alpha,
                    const float* resid, int ldr, int relu,
                    float* C, int ldc, long long sC, int batch) {
    dim3 grid(Nn / 128, M / 128, batch), blk(256);
    gemm_kernel<128, 128, 16, 8, 8, true><<<grid, blk>>>(
        M, Nn, K, A, lda, sA, B, ldb, sB, bias, alpha, resid, ldr, relu, C, ldc, sC);
}
static void gemm_nb64(int M, int Nn, int K,
                      const float* A, int lda, long long sA,
                      const float* B, int ldb, long long sB,
                      float* C, int ldc, long long sC, int batch) {
    dim3 grid(Nn / 64, M / 128, batch), blk(256);
    gemm_kernel<128, 64, 16, 8, 4, false><<<grid, blk>>>(
        M, Nn, K, A, lda, sA, B, ldb, sB, nullptr, 1.f, nullptr, 0, 0, C, ldc, sC);
}

extern "C" void kernel_launch(void* const* d_in, const int* in_sizes, int n_in,
                              void* d_out, int out_size) {
    const float* key_in    = (const float*)d_in[0];
    const float* value_in  = (const float*)d_in[1];
    const float* query     = (const float*)d_in[2];
    const float* in_proj_w = (const float*)d_in[3];
    const float* in_proj_b = (const float*)d_in[4];
    const float* out_w     = (const float*)d_in[5];
    const float* out_b     = (const float*)d_in[6];
    const float* ln1_g     = (const float*)d_in[7];
    const float* ln1_b     = (const float*)d_in[8];
    const float* ln2_g     = (const float*)d_in[9];
    const float* ln2_b     = (const float*)d_in[10];
    const float* ff1_w     = (const float*)d_in[11];
    const float* ff1_b     = (const float*)d_in[12];
    const float* ff2_w     = (const float*)d_in[13];
    const float* ff2_b     = (const float*)d_in[14];
    float* out = (float*)d_out;

    float *q, *k, *v, *w, *wpad, *attn, *x1, *x, *hbuf, *y, *tgt, *noise;
    cudaGetSymbolAddress((void**)&q,     g_q);
    cudaGetSymbolAddress((void**)&k,     g_k);
    cudaGetSymbolAddress((void**)&v,     g_v);
    cudaGetSymbolAddress((void**)&w,     g_w);
    cudaGetSymbolAddress((void**)&wpad,  g_wpad);
    cudaGetSymbolAddress((void**)&attn,  g_attn);
    cudaGetSymbolAddress((void**)&x1,    g_x1);
    cudaGetSymbolAddress((void**)&x,     g_x);
    cudaGetSymbolAddress((void**)&hbuf,  g_h);
    cudaGetSymbolAddress((void**)&y,     g_y);
    cudaGetSymbolAddress((void**)&tgt,   g_tgt);
    cudaGetSymbolAddress((void**)&noise, g_noise);

    noise_kernel<<<(NL * 2048 + 255) / 256, 256>>>(noise);

    for (int i = 0; i < NL; i++) {
        const float* tin = (i == 0) ? query : tgt;
        const float* W   = in_proj_w + (size_t)i * 3 * DDIM * DDIM;
        const float* Bb  = in_proj_b + (size_t)i * 3 * DDIM;

        // q = (tgt @ Wq^T + bq) * scaling ; k,v projections
        gemm_tb(ROWS_T, DDIM, DDIM, tin,      DDIM, 0, W,                 DDIM, 0,
                Bb,            SCALING, nullptr, 0, 0, q, DDIM, 0, 1);
        gemm_tb(ROWS_S, DDIM, DDIM, key_in,   DDIM, 0, W +     DDIM*DDIM, DDIM, 0,
                Bb + DDIM,     1.f,     nullptr, 0, 0, k, DDIM, 0, 1);
        gemm_tb(ROWS_S, DDIM, DDIM, value_in, DDIM, 0, W + 2 * DDIM*DDIM, DDIM, 0,
                Bb + 2 * DDIM, 1.f,     nullptr, 0, 0, v, DDIM, 0, 1);

        // scores[n,h,l,s] = q . k   (batched over z=n*H+h; view offset = z*64)
        gemm_tb(LLQ, SS, HDIM, q, NB * DDIM, 64, k, NB * DDIM, 64,
                nullptr, 1.f, nullptr, 0, 0, w, SS, (long long)LLQ * SS, NB * HH);

        softmax_kernel<<<NB * HH * LLQ, 256>>>(w, wpad);

        if (i == NL - 1)
            attnmap_kernel<<<((long long)NB * LLQ * SS + 255) / 256, 256>>>(
                w, out + (size_t)ROWS_T * DDIM);

        // attn[l,n,h,d] = sum_s w * v  (+ noise pad row added next)
        gemm_nb64(LLQ, HDIM, SS, w, SS, (long long)LLQ * SS,
                  v, NB * DDIM, 64, attn, NB * DDIM, 64, NB * HH);
        addnoise_kernel<<<((long long)ROWS_T * DDIM + 255) / 256, 256>>>(
            attn, wpad, noise + (size_t)i * NB * HH * HDIM);

        // out-proj + residual -> LN1
        gemm_tb(ROWS_T, DDIM, DDIM, attn, DDIM, 0, out_w + (size_t)i * DDIM * DDIM,
                DDIM, 0, out_b + i * DDIM, 1.f, tin, DDIM, 0, x1, DDIM, 0, 1);
        ln_kernel<<<ROWS_T, 256>>>(x1, ln1_g + i * DDIM, ln1_b + i * DDIM, x);

        // FFN
        gemm_tb(ROWS_T, FFD, DDIM, x, DDIM, 0, ff1_w + (size_t)i * FFD * DDIM,
                DDIM, 0, ff1_b + i * FFD, 1.f, nullptr, 0, 1, hbuf, FFD, 0, 1);
        gemm_tb(ROWS_T, DDIM, FFD, hbuf, FFD, 0, ff2_w + (size_t)i * DDIM * FFD,
                FFD, 0, ff2_b + i * DDIM, 1.f, x, DDIM, 0, y, DDIM, 0, 1);

        float* dst = (i == NL - 1) ? out : tgt;
        ln_kernel<<<ROWS_T, 256>>>(y, ln2_g + i * DDIM, ln2_b + i * DDIM, dst);
    }
}

// round 7
// speedup vs baseline: 2.6660x; 2.6660x over previous
#include <cuda_runtime.h>
#include <cstdint>
#include <math.h>

// ---------------- problem constants ----------------
#define NL   2
#define DDIM 1024
#define HH   16
#define HDIM 64
#define FFD  4096
#define SS   1024
#define NB   2
#define LLQ  4096
#define ROWS_T (LLQ*NB)   // 8192 query rows
#define ROWS_S (SS*NB)    // 2048 kv rows
#define SCALING 0.125f    // HD^-0.5

// ---------------- device scratch (static, allocation-free) ----------------
__device__ float g_q   [ROWS_T*DDIM];
__device__ float g_k   [ROWS_S*DDIM];
__device__ float g_v   [ROWS_S*DDIM];
__device__ float g_w   [134217728];      // NB*HH*LLQ*SS attention weights (512MB)
__device__ float g_wpad[NB*HH*LLQ];
__device__ float g_attn[ROWS_T*DDIM];
__device__ float g_x1  [ROWS_T*DDIM];
__device__ float g_x   [ROWS_T*DDIM];
__device__ float g_h   [ROWS_T*FFD];
__device__ float g_y   [ROWS_T*DDIM];
__device__ float g_tgt [ROWS_T*DDIM];
__device__ float g_noise[NL*NB*HH*HDIM];

// ---------------- TF32 rounding ----------------
__device__ __forceinline__ float tf32r(float x) {
    asm("cvt.rna.tf32.f32 %0, %0;" : "+f"(x));
    return x;
}

// ---------------- JAX threefry2x32 (partitionable) ----------------
__device__ __forceinline__ uint32_t rotl32(uint32_t x, int d) {
    return (x << d) | (x >> (32 - d));
}
__device__ __forceinline__ void threefry2x32(uint32_t k0, uint32_t k1,
                                             uint32_t& x0, uint32_t& x1) {
    uint32_t ks2 = k0 ^ k1 ^ 0x1BD11BDAu;
    x0 += k0; x1 += k1;
#define TFR(r) { x0 += x1; x1 = rotl32(x1, (r)); x1 ^= x0; }
    TFR(13) TFR(15) TFR(26) TFR(6)
    x0 += k1; x1 += ks2 + 1u;
    TFR(17) TFR(29) TFR(16) TFR(24)
    x0 += ks2; x1 += k0 + 2u;
    TFR(13) TFR(15) TFR(26) TFR(6)
    x0 += k0; x1 += k1 + 3u;
    TFR(17) TFR(29) TFR(16) TFR(24)
    x0 += k1; x1 += ks2 + 4u;
    TFR(13) TFR(15) TFR(26) TFR(6)
    x0 += ks2; x1 += k0 + 5u;
#undef TFR
}
__device__ __forceinline__ float bits_to_normal(uint32_t b) {
    float f = __uint_as_float((b >> 9) | 0x3F800000u) - 1.0f;   // [0,1)
    const float lo = -0.99999994f;
    float u = fmaxf(lo, f * 2.0f + lo);
    return 1.4142135623730951f * erfinvf(u);
}
// bits[j] = y0 ^ y1, (y0,y1) = threefry2x32(key, (0, j))
__global__ void noise_kernel(float* __restrict__ noise) {
    int j = blockIdx.x * blockDim.x + threadIdx.x;
    if (j >= NL * 2048) return;
    int layer = j / 2048, jj = j % 2048;
    uint32_t k0 = 0u, k1 = 42u, x0 = 0u, x1 = (uint32_t)layer;
    threefry2x32(k0, k1, x0, x1);
    uint32_t b0 = 0u, b1 = (uint32_t)jj;
    threefry2x32(x0, x1, b0, b1);
    noise[layer * 2048 + jj] = bits_to_normal(b0 ^ b1);
}

// ---------------- TF32 tensor-core GEMM (mma.sync.m16n8k8) ----------------
__device__ __forceinline__ void mma_tf32(float* d, const uint32_t* a, const uint32_t* b) {
    asm volatile(
        "mma.sync.aligned.m16n8k8.row.col.f32.tf32.tf32.f32 "
        "{%0,%1,%2,%3}, {%4,%5,%6,%7}, {%8,%9}, {%0,%1,%2,%3};\n"
        : "+f"(d[0]), "+f"(d[1]), "+f"(d[2]), "+f"(d[3])
        : "r"(a[0]), "r"(a[1]), "r"(a[2]), "r"(a[3]), "r"(b[0]), "r"(b[1]));
}

// C[m,n] = epi( alpha*(sum_k A[m,k]*B(k,n) + bias[n]) + resid[m,n] )
// TRANSB: B is (N,K) row-major; else B is (K,N) row-major.
// Smem: A and trans-B stored row-major stride 36 (36 mod 32 == 4: fragment
// LDS banks 4g+tq injective); non-trans B stored k-major stride BN+8
// (mod 32 == 8: banks 8tq+g injective). All STS are coalesced float4.
template<int BM, int BN, int WM, int WN, bool TRANSB>
__global__ __launch_bounds__(256, 2)
void mma_gemm(int M, int Nn, int K,
              const float* __restrict__ A, int lda, long long sA,
              const float* __restrict__ B, int ldb, long long sB,
              const float* __restrict__ bias, float alpha,
              const float* __restrict__ resid, int ldr, int relu,
              float* __restrict__ C, int ldc, long long sC)
{
    constexpr int BK = 32;
    constexpr int SA = BK + 4;                      // 36
    constexpr int SBT = BK + 4;                     // trans-B stride 36
    constexpr int SBN = BN + 8;                     // non-trans B stride
    constexpr int BSZ = TRANSB ? (BN * SBT) : (BK * SBN);

    __shared__ __align__(16) float As[BM * SA];
    __shared__ __align__(16) float Bs[BSZ];

    long long bz = blockIdx.z;
    A += bz * sA; B += bz * sB; C += bz * sC;
    const int bm = blockIdx.y * BM;
    const int bn = blockIdx.x * BN;
    const int tid = threadIdx.x;
    const int wid = tid >> 5, lane = tid & 31;
    const int g = lane >> 2, tq = lane & 3;
    constexpr int WX = BN / WN;
    const int wm = (wid / WX) * WM, wn = (wid % WX) * WN;
    constexpr int MA = WM / 16, NA = WN / 8;

    float acc[MA][NA][4];
#pragma unroll
    for (int i = 0; i < MA; i++)
#pragma unroll
        for (int j = 0; j < NA; j++)
#pragma unroll
            for (int e = 0; e < 4; e++) acc[i][j][e] = 0.f;

    const uint32_t* ua = reinterpret_cast<const uint32_t*>(As);
    const uint32_t* ub = reinterpret_cast<const uint32_t*>(Bs);

    for (int k0 = 0; k0 < K; k0 += BK) {
        // ---- A tile: BM x BK, row-major stride SA ----
#pragma unroll
        for (int it = 0; it < BM * BK / (4 * 256); it++) {
            int vi = tid + it * 256;
            int r  = vi >> 3;
            int kc = (vi & 7) * 4;
            float4 t = *reinterpret_cast<const float4*>(
                A + (long long)(bm + r) * lda + k0 + kc);
            t.x = tf32r(t.x); t.y = tf32r(t.y);
            t.z = tf32r(t.z); t.w = tf32r(t.w);
            *reinterpret_cast<float4*>(&As[r * SA + kc]) = t;
        }
        // ---- B tile ----
        if (TRANSB) {
#pragma unroll
            for (int it = 0; it < BN * BK / (4 * 256); it++) {
                int vi = tid + it * 256;
                int r  = vi >> 3;
                int kc = (vi & 7) * 4;
                float4 t = *reinterpret_cast<const float4*>(
                    B + (long long)(bn + r) * ldb + k0 + kc);
                t.x = tf32r(t.x); t.y = tf32r(t.y);
                t.z = tf32r(t.z); t.w = tf32r(t.w);
                *reinterpret_cast<float4*>(&Bs[r * SBT + kc]) = t;
            }
        } else {
#pragma unroll
            for (int it = 0; it < BK * BN / (4 * 256); it++) {
                int vi = tid + it * 256;
                int kk = vi / (BN / 4);
                int c  = (vi % (BN / 4)) * 4;
                float4 t = *reinterpret_cast<const float4*>(
                    B + (long long)(k0 + kk) * ldb + bn + c);
                t.x = tf32r(t.x); t.y = tf32r(t.y);
                t.z = tf32r(t.z); t.w = tf32r(t.w);
                *reinterpret_cast<float4*>(&Bs[kk * SBN + c]) = t;
            }
        }
        __syncthreads();

#pragma unroll
        for (int ka = 0; ka < BK / 8; ka++) {
            const int kb = ka * 8;
            uint32_t af[MA][4];
            uint32_t bf[NA][2];
#pragma unroll
            for (int ma = 0; ma < MA; ma++) {
                int mr = wm + ma * 16 + g;
                af[ma][0] = ua[mr * SA + kb + tq];
                af[ma][1] = ua[(mr + 8) * SA + kb + tq];
                af[ma][2] = ua[mr * SA + kb + tq + 4];
                af[ma][3] = ua[(mr + 8) * SA + kb + tq + 4];
            }
#pragma unroll
            for (int na = 0; na < NA; na++) {
                int nc = wn + na * 8 + g;
                if (TRANSB) {
                    bf[na][0] = ub[nc * SBT + kb + tq];
                    bf[na][1] = ub[nc * SBT + kb + tq + 4];
                } else {
                    bf[na][0] = ub[(kb + tq) * SBN + nc];
                    bf[na][1] = ub[(kb + tq + 4) * SBN + nc];
                }
            }
#pragma unroll
            for (int ma = 0; ma < MA; ma++)
#pragma unroll
                for (int na = 0; na < NA; na++)
                    mma_tf32(acc[ma][na], af[ma], bf[na]);
        }
        __syncthreads();
    }

    // ---- epilogue ----
#pragma unroll
    for (int ma = 0; ma < MA; ma++) {
#pragma unroll
        for (int na = 0; na < NA; na++) {
            int c0 = bn + wn + na * 8 + tq * 2;
#pragma unroll
            for (int hh = 0; hh < 2; hh++) {
                long long rr = bm + wm + ma * 16 + g + hh * 8;
                float v0 = acc[ma][na][hh * 2 + 0];
                float v1 = acc[ma][na][hh * 2 + 1];
                if (bias) { v0 += bias[c0]; v1 += bias[c0 + 1]; }
                v0 *= alpha; v1 *= alpha;
                if (resid) {
                    float2 rv = *reinterpret_cast<const float2*>(
                        resid + rr * (long long)ldr + c0);
                    v0 += rv.x; v1 += rv.y;
                }
                if (relu) { v0 = fmaxf(v0, 0.f); v1 = fmaxf(v1, 0.f); }
                *reinterpret_cast<float2*>(C + rr * (long long)ldc + c0) =
                    make_float2(v0, v1);
            }
        }
    }
}

// ---------------- softmax over S=1024 (+ implicit zero pad column) ----------------
__global__ void softmax_kernel(float* __restrict__ w, float* __restrict__ wpad) {
    long long row = blockIdx.x;
    float4* p = reinterpret_cast<float4*>(w + row * (long long)SS);
    int t = threadIdx.x;
    float4 v = p[t];
    __shared__ float red[256];
    float m = fmaxf(fmaxf(v.x, v.y), fmaxf(v.z, v.w));
    red[t] = m; __syncthreads();
    for (int o = 128; o > 0; o >>= 1) {
        if (t < o) red[t] = fmaxf(red[t], red[t + o]);
        __syncthreads();
    }
    m = fmaxf(red[0], 0.f);
    __syncthreads();
    v.x = expf(v.x - m); v.y = expf(v.y - m);
    v.z = expf(v.z - m); v.w = expf(v.w - m);
    red[t] = v.x + v.y + v.z + v.w; __syncthreads();
    for (int o = 128; o > 0; o >>= 1) {
        if (t < o) red[t] += red[t + o];
        __syncthreads();
    }
    float epad = expf(-m);
    float inv = 1.f / (red[0] + epad);
    v.x *= inv; v.y *= inv; v.z *= inv; v.w *= inv;
    p[t] = v;
    if (t == 0) wpad[row] = epad * inv;
}

// ---------------- layernorm over D=1024 ----------------
__global__ void ln_kernel(const float* __restrict__ x, const float* __restrict__ g,
                          const float* __restrict__ b, float* __restrict__ y) {
    long long row = blockIdx.x;
    const float4* px = reinterpret_cast<const float4*>(x + row * (long long)DDIM);
    int t = threadIdx.x;
    float4 v = px[t];
    __shared__ float r1[256], r2[256];
    r1[t] = v.x + v.y + v.z + v.w;
    r2[t] = v.x*v.x + v.y*v.y + v.z*v.z + v.w*v.w;
    __syncthreads();
    for (int o = 128; o > 0; o >>= 1) {
        if (t < o) { r1[t] += r1[t + o]; r2[t] += r2[t + o]; }
        __syncthreads();
    }
    float mu  = r1[0] * (1.f / DDIM);
    float var = r2[0] * (1.f / DDIM) - mu * mu;
    float rs  = rsqrtf(var + 1e-5f);
    float4 gg = reinterpret_cast<const float4*>(g)[t];
    float4 bb = reinterpret_cast<const float4*>(b)[t];
    float4 o4;
    o4.x = (v.x - mu) * rs * gg.x + bb.x;
    o4.y = (v.y - mu) * rs * gg.y + bb.y;
    o4.z = (v.z - mu) * rs * gg.z + bb.z;
    o4.w = (v.w - mu) * rs * gg.w + bb.w;
    reinterpret_cast<float4*>(y + row * (long long)DDIM)[t] = o4;
}

// ---------------- attn_map = mean_h sigmoid(w) ----------------
__global__ void attnmap_kernel(const float* __restrict__ w, float* __restrict__ out) {
    long long idx = (long long)blockIdx.x * blockDim.x + threadIdx.x;
    if (idx >= (long long)NB * LLQ * SS) return;
    int s = (int)(idx & (SS - 1));
    long long t2 = idx >> 10;
    int l = (int)(t2 & (LLQ - 1));
    int n = (int)(t2 >> 12);
    float acc = 0.f;
#pragma unroll
    for (int h = 0; h < HH; h++) {
        float v = w[(((long long)(n * HH + h) * LLQ + l) << 10) + s];
        acc += 1.f / (1.f + expf(-v));
    }
    out[idx] = acc * (1.f / HH);
}

// ---------------- add pad-column noise contribution ----------------
__global__ void addnoise_kernel(float* __restrict__ attn,
                                const float* __restrict__ wpad,
                                const float* __restrict__ noise) {
    long long idx = (long long)blockIdx.x * blockDim.x + threadIdx.x;
    if (idx >= (long long)ROWS_T * DDIM) return;
    int c = (int)(idx & 1023);
    long long r = idx >> 10;
    int n = (int)(r & 1);
    int l = (int)(r >> 1);
    int h = c >> 6, d = c & 63;
    attn[idx] += wpad[(n * HH + h) * LLQ + l] * noise[(n * HH + h) * HDIM + d];
}

// ---------------- host launchers ----------------
static void gemm_tb(int M, int Nn, int K,
                    const float* A, int lda, long long sA,
                    const float* B, int ldb, long long sB,
                    const float* bias, float alpha,
                    const float* resid, int ldr, int relu,
                    float* C, int ldc, long long sC, int batch) {
    dim3 grid(Nn / 128, M / 128, batch), blk(256);
    mma_gemm<128, 128, 64, 32, true><<<grid, blk>>>(
        M, Nn, K, A, lda, sA, B, ldb, sB, bias, alpha, resid, ldr, relu, C, ldc, sC);
}
static void gemm_nb64(int M, int Nn, int K,
                      const float* A, int lda, long long sA,
                      const float* B, int ldb, long long sB,
                      float* C, int ldc, long long sC, int batch) {
    dim3 grid(Nn / 64, M / 128, batch), blk(256);
    mma_gemm<128, 64, 64, 16, false><<<grid, blk>>>(
        M, Nn, K, A, lda, sA, B, ldb, sB, nullptr, 1.f, nullptr, 0, 0, C, ldc, sC);
}

extern "C" void kernel_launch(void* const* d_in, const int* in_sizes, int n_in,
                              void* d_out, int out_size) {
    const float* key_in    = (const float*)d_in[0];
    const float* value_in  = (const float*)d_in[1];
    const float* query     = (const float*)d_in[2];
    const float* in_proj_w = (const float*)d_in[3];
    const float* in_proj_b = (const float*)d_in[4];
    const float* out_w     = (const float*)d_in[5];
    const float* out_b     = (const float*)d_in[6];
    const float* ln1_g     = (const float*)d_in[7];
    const float* ln1_b     = (const float*)d_in[8];
    const float* ln2_g     = (const float*)d_in[9];
    const float* ln2_b     = (const float*)d_in[10];
    const float* ff1_w     = (const float*)d_in[11];
    const float* ff1_b     = (const float*)d_in[12];
    const float* ff2_w     = (const float*)d_in[13];
    const float* ff2_b     = (const float*)d_in[14];
    float* out = (float*)d_out;

    float *q, *k, *v, *w, *wpad, *attn, *x1, *x, *hbuf, *y, *tgt, *noise;
    cudaGetSymbolAddress((void**)&q,     g_q);
    cudaGetSymbolAddress((void**)&k,     g_k);
    cudaGetSymbolAddress((void**)&v,     g_v);
    cudaGetSymbolAddress((void**)&w,     g_w);
    cudaGetSymbolAddress((void**)&wpad,  g_wpad);
    cudaGetSymbolAddress((void**)&attn,  g_attn);
    cudaGetSymbolAddress((void**)&x1,    g_x1);
    cudaGetSymbolAddress((void**)&x,     g_x);
    cudaGetSymbolAddress((void**)&hbuf,  g_h);
    cudaGetSymbolAddress((void**)&y,     g_y);
    cudaGetSymbolAddress((void**)&tgt,   g_tgt);
    cudaGetSymbolAddress((void**)&noise, g_noise);

    noise_kernel<<<(NL * 2048 + 255) / 256, 256>>>(noise);

    for (int i = 0; i < NL; i++) {
        const float* tin = (i == 0) ? query : tgt;
        const float* W   = in_proj_w + (size_t)i * 3 * DDIM * DDIM;
        const float* Bb  = in_proj_b + (size_t)i * 3 * DDIM;

        // q = (tgt @ Wq^T + bq) * scaling ; k,v projections
        gemm_tb(ROWS_T, DDIM, DDIM, tin,      DDIM, 0, W,                 DDIM, 0,
                Bb,            SCALING, nullptr, 0, 0, q, DDIM, 0, 1);
        gemm_tb(ROWS_S, DDIM, DDIM, key_in,   DDIM, 0, W +     DDIM*DDIM, DDIM, 0,
                Bb + DDIM,     1.f,     nullptr, 0, 0, k, DDIM, 0, 1);
        gemm_tb(ROWS_S, DDIM, DDIM, value_in, DDIM, 0, W + 2 * DDIM*DDIM, DDIM, 0,
                Bb + 2 * DDIM, 1.f,     nullptr, 0, 0, v, DDIM, 0, 1);

        // scores[n,h,l,s] = q . k  (batched over z=n*H+h; view offset = z*64)
        gemm_tb(LLQ, SS, HDIM, q, NB * DDIM, 64, k, NB * DDIM, 64,
                nullptr, 1.f, nullptr, 0, 0, w, SS, (long long)LLQ * SS, NB * HH);

        softmax_kernel<<<NB * HH * LLQ, 256>>>(w, wpad);

        if (i == NL - 1)
            attnmap_kernel<<<((long long)NB * LLQ * SS + 255) / 256, 256>>>(
                w, out + (size_t)ROWS_T * DDIM);

        // attn[l,n,h,d] = sum_s w * v  (+ noise pad row added next)
        gemm_nb64(LLQ, HDIM, SS, w, SS, (long long)LLQ * SS,
                  v, NB * DDIM, 64, attn, NB * DDIM, 64, NB * HH);
        addnoise_kernel<<<((long long)ROWS_T * DDIM + 255) / 256, 256>>>(
            attn, wpad, noise + (size_t)i * NB * HH * HDIM);

        // out-proj + residual -> LN1
        gemm_tb(ROWS_T, DDIM, DDIM, attn, DDIM, 0, out_w + (size_t)i * DDIM * DDIM,
                DDIM, 0, out_b + i * DDIM, 1.f, tin, DDIM, 0, x1, DDIM, 0, 1);
        ln_kernel<<<ROWS_T, 256>>>(x1, ln1_g + i * DDIM, ln1_b + i * DDIM, x);

        // FFN
        gemm_tb(ROWS_T, FFD, DDIM, x, DDIM, 0, ff1_w + (size_t)i * FFD * DDIM,
                DDIM, 0, ff1_b + i * FFD, 1.f, nullptr, 0, 1, hbuf, FFD, 0, 1);
        gemm_tb(ROWS_T, DDIM, FFD, hbuf, FFD, 0, ff2_w + (size_t)i * DDIM * FFD,
                FFD, 0, ff2_b + i * DDIM, 1.f, x, DDIM, 0, y, DDIM, 0, 1);

        float* dst = (i == NL - 1) ? out : tgt;
        ln_kernel<<<ROWS_T, 256>>>(y, ln2_g + i * DDIM, ln2_b + i * DDIM, dst);
    }
}

// round 10
// speedup vs baseline: 2.9166x; 1.0940x over previous
#include <cuda_runtime.h>
#include <cstdint>
#include <math.h>

// ---------------- problem constants ----------------
#define NL   2
#define DDIM 1024
#define HH   16
#define HDIM 64
#define FFD  4096
#define SS   1024
#define NB   2
#define LLQ  4096
#define ROWS_T (LLQ*NB)   // 8192 query rows
#define ROWS_S (SS*NB)    // 2048 kv rows
#define SCALING 0.125f    // HD^-0.5

// ---------------- device scratch (static, allocation-free) ----------------
__device__ float g_q   [ROWS_T*DDIM];
__device__ float g_k   [ROWS_S*DDIM];
__device__ float g_v   [ROWS_S*DDIM];
__device__ float g_w   [134217728];      // NB*HH*LLQ*SS attention weights (512MB)
__device__ float g_wpad[NB*HH*LLQ];
__device__ float g_attn[ROWS_T*DDIM];
__device__ float g_x1  [ROWS_T*DDIM];
__device__ float g_x   [ROWS_T*DDIM];
__device__ float g_h   [ROWS_T*FFD];
__device__ float g_y   [ROWS_T*DDIM];
__device__ float g_tgt [ROWS_T*DDIM];
__device__ float g_noise[NL*NB*HH*HDIM];

// ---------------- TF32 rounding ----------------
__device__ __forceinline__ uint32_t tf32bits(uint32_t x) {
    float f = __uint_as_float(x);
    asm("cvt.rna.tf32.f32 %0, %0;" : "+f"(f));
    return __float_as_uint(f);
}

// ---------------- cp.async helpers ----------------
__device__ __forceinline__ void cp16(void* s, const void* g) {
    uint32_t sa = (uint32_t)__cvta_generic_to_shared(s);
    asm volatile("cp.async.cg.shared.global [%0], [%1], 16;" :: "r"(sa), "l"(g));
}
__device__ __forceinline__ void cp_commit() {
    asm volatile("cp.async.commit_group;");
}
template<int N>
__device__ __forceinline__ void cp_wait() {
    asm volatile("cp.async.wait_group %0;" :: "n"(N));
}

// ---------------- JAX threefry2x32 (partitionable) ----------------
__device__ __forceinline__ uint32_t rotl32(uint32_t x, int d) {
    return (x << d) | (x >> (32 - d));
}
__device__ __forceinline__ void threefry2x32(uint32_t k0, uint32_t k1,
                                             uint32_t& x0, uint32_t& x1) {
    uint32_t ks2 = k0 ^ k1 ^ 0x1BD11BDAu;
    x0 += k0; x1 += k1;
#define TFR(r) { x0 += x1; x1 = rotl32(x1, (r)); x1 ^= x0; }
    TFR(13) TFR(15) TFR(26) TFR(6)
    x0 += k1; x1 += ks2 + 1u;
    TFR(17) TFR(29) TFR(16) TFR(24)
    x0 += ks2; x1 += k0 + 2u;
    TFR(13) TFR(15) TFR(26) TFR(6)
    x0 += k0; x1 += k1 + 3u;
    TFR(17) TFR(29) TFR(16) TFR(24)
    x0 += k1; x1 += ks2 + 4u;
    TFR(13) TFR(15) TFR(26) TFR(6)
    x0 += ks2; x1 += k0 + 5u;
#undef TFR
}
__device__ __forceinline__ float bits_to_normal(uint32_t b) {
    float f = __uint_as_float((b >> 9) | 0x3F800000u) - 1.0f;   // [0,1)
    const float lo = -0.99999994f;
    float u = fmaxf(lo, f * 2.0f + lo);
    return 1.4142135623730951f * erfinvf(u);
}
// bits[j] = y0 ^ y1, (y0,y1) = threefry2x32(key, (0, j))
__global__ void noise_kernel(float* __restrict__ noise) {
    int j = blockIdx.x * blockDim.x + threadIdx.x;
    if (j >= NL * 2048) return;
    int layer = j / 2048, jj = j % 2048;
    uint32_t k0 = 0u, k1 = 42u, x0 = 0u, x1 = (uint32_t)layer;
    threefry2x32(k0, k1, x0, x1);
    uint32_t b0 = 0u, b1 = (uint32_t)jj;
    threefry2x32(x0, x1, b0, b1);
    noise[layer * 2048 + jj] = bits_to_normal(b0 ^ b1);
}

// ---------------- TF32 tensor-core GEMM (mma.sync.m16n8k8) ----------------
__device__ __forceinline__ void mma_tf32(float* d, const uint32_t* a, const uint32_t* b) {
    asm volatile(
        "mma.sync.aligned.m16n8k8.row.col.f32.tf32.tf32.f32 "
        "{%0,%1,%2,%3}, {%4,%5,%6,%7}, {%8,%9}, {%0,%1,%2,%3};\n"
        : "+f"(d[0]), "+f"(d[1]), "+f"(d[2]), "+f"(d[3])
        : "r"(a[0]), "r"(a[1]), "r"(a[2]), "r"(a[3]), "r"(b[0]), "r"(b[1]));
}

// C[m,n] = epi( alpha*(sum_k A[m,k]*B(k,n) + bias[n]) + resid[m,n] )
// TRANSB: B is (N,K) row-major; else B is (K,N) row-major.
// 2-stage cp.async double buffering; tf32 rounding at fragment load.
// Smem: A and trans-B row-major stride 36 (mod 32 == 4: banks 4g+tq injective);
// non-trans B k-major stride BN+8 (mod 32 == 8: banks 8tq+g injective).
template<int BM, int BN, int WM, int WN, bool TRANSB>
__global__ __launch_bounds__(256, 2)
void mma_gemm(int M, int Nn, int K,
              const float* __restrict__ A, int lda, long long sA,
              const float* __restrict__ B, int ldb, long long sB,
              const float* __restrict__ bias, float alpha,
              const float* __restrict__ resid, int ldr, int relu,
              float* __restrict__ C, int ldc, long long sC)
{
    constexpr int BK = 32;
    constexpr int SA  = BK + 4;                     // 36
    constexpr int SBT = BK + 4;                     // trans-B stride 36
    constexpr int SBN = BN + 8;                     // non-trans B stride
    constexpr int ASTG = BM * SA;                   // floats per A stage
    constexpr int BSTG = TRANSB ? (BN * SBT) : (BK * SBN);

    extern __shared__ __align__(16) float smem[];
    float* As = smem;                               // 2 stages
    float* Bs = smem + 2 * ASTG;                    // 2 stages

    long long bz = blockIdx.z;
    A += bz * sA; B += bz * sB; C += bz * sC;
    const int bm = blockIdx.y * BM;
    const int bn = blockIdx.x * BN;
    const int tid = threadIdx.x;
    const int wid = tid >> 5, lane = tid & 31;
    const int g = lane >> 2, tq = lane & 3;
    constexpr int WX = BN / WN;
    const int wm = (wid / WX) * WM, wn = (wid % WX) * WN;
    constexpr int MA = WM / 16, NA = WN / 8;

    float acc[MA][NA][4];
#pragma unroll
    for (int i = 0; i < MA; i++)
#pragma unroll
        for (int j = 0; j < NA; j++)
#pragma unroll
            for (int e = 0; e < 4; e++) acc[i][j][e] = 0.f;

    // ---- tile loader: issues cp.async for stage `st`, k-offset k0 ----
    auto load_tiles = [&](int st, int k0) {
        float* as = As + st * ASTG;
        float* bs = Bs + st * BSTG;
#pragma unroll
        for (int it = 0; it < BM * BK / (4 * 256); it++) {
            int vi = tid + it * 256;
            int r  = vi >> 3;
            int kc = (vi & 7) * 4;
            cp16(&as[r * SA + kc], A + (long long)(bm + r) * lda + k0 + kc);
        }
        if (TRANSB) {
#pragma unroll
            for (int it = 0; it < BN * BK / (4 * 256); it++) {
                int vi = tid + it * 256;
                int r  = vi >> 3;
                int kc = (vi & 7) * 4;
                cp16(&bs[r * SBT + kc], B + (long long)(bn + r) * ldb + k0 + kc);
            }
        } else {
#pragma unroll
            for (int it = 0; it < BK * BN / (4 * 256); it++) {
                int vi = tid + it * 256;
                int kk = vi / (BN / 4);
                int c  = (vi % (BN / 4)) * 4;
                cp16(&bs[kk * SBN + c], B + (long long)(k0 + kk) * ldb + bn + c);
            }
        }
    };

    const int nk = K / BK;
    load_tiles(0, 0);
    cp_commit();

    for (int i = 0; i < nk; i++) {
        const int buf = i & 1;
        if (i + 1 < nk) {
            load_tiles(buf ^ 1, (i + 1) * BK);
            cp_commit();
            cp_wait<1>();
        } else {
            cp_wait<0>();
        }
        __syncthreads();

        const uint32_t* ua = reinterpret_cast<const uint32_t*>(As + buf * ASTG);
        const uint32_t* ub = reinterpret_cast<const uint32_t*>(Bs + buf * BSTG);

#pragma unroll
        for (int ka = 0; ka < BK / 8; ka++) {
            const int kb = ka * 8;
            uint32_t af[MA][4];
            uint32_t bf[NA][2];
#pragma unroll
            for (int ma = 0; ma < MA; ma++) {
                int mr = wm + ma * 16 + g;
                af[ma][0] = tf32bits(ua[mr * SA + kb + tq]);
                af[ma][1] = tf32bits(ua[(mr + 8) * SA + kb + tq]);
                af[ma][2] = tf32bits(ua[mr * SA + kb + tq + 4]);
                af[ma][3] = tf32bits(ua[(mr + 8) * SA + kb + tq + 4]);
            }
#pragma unroll
            for (int na = 0; na < NA; na++) {
                int nc = wn + na * 8 + g;
                if (TRANSB) {
                    bf[na][0] = tf32bits(ub[nc * SBT + kb + tq]);
                    bf[na][1] = tf32bits(ub[nc * SBT + kb + tq + 4]);
                } else {
                    bf[na][0] = tf32bits(ub[(kb + tq) * SBN + nc]);
                    bf[na][1] = tf32bits(ub[(kb + tq + 4) * SBN + nc]);
                }
            }
#pragma unroll
            for (int ma = 0; ma < MA; ma++)
#pragma unroll
                for (int na = 0; na < NA; na++)
                    mma_tf32(acc[ma][na], af[ma], bf[na]);
        }
        __syncthreads();   // all warps done with `buf` before it is refilled
    }

    // ---- epilogue ----
#pragma unroll
    for (int ma = 0; ma < MA; ma++) {
#pragma unroll
        for (int na = 0; na < NA; na++) {
            int c0 = bn + wn + na * 8 + tq * 2;
#pragma unroll
            for (int hh = 0; hh < 2; hh++) {
                long long rr = bm + wm + ma * 16 + g + hh * 8;
                float v0 = acc[ma][na][hh * 2 + 0];
                float v1 = acc[ma][na][hh * 2 + 1];
                if (bias) { v0 += bias[c0]; v1 += bias[c0 + 1]; }
                v0 *= alpha; v1 *= alpha;
                if (resid) {
                    float2 rv = *reinterpret_cast<const float2*>(
                        resid + rr * (long long)ldr + c0);
                    v0 += rv.x; v1 += rv.y;
                }
                if (relu) { v0 = fmaxf(v0, 0.f); v1 = fmaxf(v1, 0.f); }
                *reinterpret_cast<float2*>(C + rr * (long long)ldc + c0) =
                    make_float2(v0, v1);
            }
        }
    }
}

// ---------------- softmax over S=1024 (+ implicit zero pad column) ----------------
__global__ void softmax_kernel(float* __restrict__ w, float* __restrict__ wpad) {
    long long row = blockIdx.x;
    float4* p = reinterpret_cast<float4*>(w + row * (long long)SS);
    int t = threadIdx.x;
    float4 v = p[t];
    __shared__ float red[256];
    float m = fmaxf(fmaxf(v.x, v.y), fmaxf(v.z, v.w));
    red[t] = m; __syncthreads();
    for (int o = 128; o > 0; o >>= 1) {
        if (t < o) red[t] = fmaxf(red[t], red[t + o]);
        __syncthreads();
    }
    m = fmaxf(red[0], 0.f);
    __syncthreads();
    v.x = expf(v.x - m); v.y = expf(v.y - m);
    v.z = expf(v.z - m); v.w = expf(v.w - m);
    red[t] = v.x + v.y + v.z + v.w; __syncthreads();
    for (int o = 128; o > 0; o >>= 1) {
        if (t < o) red[t] += red[t + o];
        __syncthreads();
    }
    float epad = expf(-m);
    float inv = 1.f / (red[0] + epad);
    v.x *= inv; v.y *= inv; v.z *= inv; v.w *= inv;
    p[t] = v;
    if (t == 0) wpad[row] = epad * inv;
}

// ---------------- layernorm over D=1024 ----------------
__global__ void ln_kernel(const float* __restrict__ x, const float* __restrict__ g,
                          const float* __restrict__ b, float* __restrict__ y) {
    long long row = blockIdx.x;
    const float4* px = reinterpret_cast<const float4*>(x + row * (long long)DDIM);
    int t = threadIdx.x;
    float4 v = px[t];
    __shared__ float r1[256], r2[256];
    r1[t] = v.x + v.y + v.z + v.w;
    r2[t] = v.x*v.x + v.y*v.y + v.z*v.z + v.w*v.w;
    __syncthreads();
    for (int o = 128; o > 0; o >>= 1) {
        if (t < o) { r1[t] += r1[t + o]; r2[t] += r2[t + o]; }
        __syncthreads();
    }
    float mu  = r1[0] * (1.f / DDIM);
    float var = r2[0] * (1.f / DDIM) - mu * mu;
    float rs  = rsqrtf(var + 1e-5f);
    float4 gg = reinterpret_cast<const float4*>(g)[t];
    float4 bb = reinterpret_cast<const float4*>(b)[t];
    float4 o4;
    o4.x = (v.x - mu) * rs * gg.x + bb.x;
    o4.y = (v.y - mu) * rs * gg.y + bb.y;
    o4.z = (v.z - mu) * rs * gg.z + bb.z;
    o4.w = (v.w - mu) * rs * gg.w + bb.w;
    reinterpret_cast<float4*>(y + row * (long long)DDIM)[t] = o4;
}

// ---------------- attn_map = mean_h sigmoid(w) ----------------
__global__ void attnmap_kernel(const float* __restrict__ w, float* __restrict__ out) {
    long long idx = (long long)blockIdx.x * blockDim.x + threadIdx.x;
    if (idx >= (long long)NB * LLQ * SS) return;
    int s = (int)(idx & (SS - 1));
    long long t2 = idx >> 10;
    int l = (int)(t2 & (LLQ - 1));
    int n = (int)(t2 >> 12);
    float acc = 0.f;
#pragma unroll
    for (int h = 0; h < HH; h++) {
        float v = w[(((long long)(n * HH + h) * LLQ + l) << 10) + s];
        acc += 1.f / (1.f + expf(-v));
    }
    out[idx] = acc * (1.f / HH);
}

// ---------------- add pad-column noise contribution ----------------
__global__ void addnoise_kernel(float* __restrict__ attn,
                                const float* __restrict__ wpad,
                                const float* __restrict__ noise) {
    long long idx = (long long)blockIdx.x * blockDim.x + threadIdx.x;
    if (idx >= (long long)ROWS_T * DDIM) return;
    int c = (int)(idx & 1023);
    long long r = idx >> 10;
    int n = (int)(r & 1);
    int l = (int)(r >> 1);
    int h = c >> 6, d = c & 63;
    attn[idx] += wpad[(n * HH + h) * LLQ + l] * noise[(n * HH + h) * HDIM + d];
}

// ---------------- host launchers ----------------
static const int SMEM_TB  = 2 * (128 * 36 + 128 * 36) * 4;   // 73728 B
static const int SMEM_NB  = 2 * (128 * 36 + 32 * 72) * 4;    // 55296 B

static void gemm_tb(int M, int Nn, int K,
                    const float* A, int lda, long long sA,
                    const float* B, int ldb, long long sB,
                    const float* bias, float alpha,
                    const float* resid, int ldr, int relu,
                    float* C, int ldc, long long sC, int batch) {
    cudaFuncSetAttribute(mma_gemm<128, 128, 64, 32, true>,
                         cudaFuncAttributeMaxDynamicSharedMemorySize, SMEM_TB);
    dim3 grid(Nn / 128, M / 128, batch), blk(256);
    mma_gemm<128, 128, 64, 32, true><<<grid, blk, SMEM_TB>>>(
        M, Nn, K, A, lda, sA, B, ldb, sB, bias, alpha, resid, ldr, relu, C, ldc, sC);
}
static void gemm_nb64(int M, int Nn, int K,
                      const float* A, int lda, long long sA,
                      const float* B, int ldb, long long sB,
                      float* C, int ldc, long long sC, int batch) {
    cudaFuncSetAttribute(mma_gemm<128, 64, 64, 16, false>,
                         cudaFuncAttributeMaxDynamicSharedMemorySize, SMEM_NB);
    dim3 grid(Nn / 64, M / 128, batch), blk(256);
    mma_gemm<128, 64, 64, 16, false><<<grid, blk, SMEM_NB>>>(
        M, Nn, K, A, lda, sA, B, ldb, sB, nullptr, 1.f, nullptr, 0, 0, C, ldc, sC);
}

extern "C" void kernel_launch(void* const* d_in, const int* in_sizes, int n_in,
                              void* d_out, int out_size) {
    const float* key_in    = (const float*)d_in[0];
    const float* value_in  = (const float*)d_in[1];
    const float* query     = (const float*)d_in[2];
    const float* in_proj_w = (const float*)d_in[3];
    const float* in_proj_b = (const float*)d_in[4];
    const float* out_w     = (const float*)d_in[5];
    const float* out_b     = (const float*)d_in[6];
    const float* ln1_g     = (const float*)d_in[7];
    const float* ln1_b     = (const float*)d_in[8];
    const float* ln2_g     = (const float*)d_in[9];
    const float* ln2_b     = (const float*)d_in[10];
    const float* ff1_w     = (const float*)d_in[11];
    const float* ff1_b     = (const float*)d_in[12];
    const float* ff2_w     = (const float*)d_in[13];
    const float* ff2_b     = (const float*)d_in[14];
    float* out = (float*)d_out;

    float *q, *k, *v, *w, *wpad, *attn, *x1, *x, *hbuf, *y, *tgt, *noise;
    cudaGetSymbolAddress((void**)&q,     g_q);
    cudaGetSymbolAddress((void**)&k,     g_k);
    cudaGetSymbolAddress((void**)&v,     g_v);
    cudaGetSymbolAddress((void**)&w,     g_w);
    cudaGetSymbolAddress((void**)&wpad,  g_wpad);
    cudaGetSymbolAddress((void**)&attn,  g_attn);
    cudaGetSymbolAddress((void**)&x1,    g_x1);
    cudaGetSymbolAddress((void**)&x,     g_x);
    cudaGetSymbolAddress((void**)&hbuf,  g_h);
    cudaGetSymbolAddress((void**)&y,     g_y);
    cudaGetSymbolAddress((void**)&tgt,   g_tgt);
    cudaGetSymbolAddress((void**)&noise, g_noise);

    noise_kernel<<<(NL * 2048 + 255) / 256, 256>>>(noise);

    for (int i = 0; i < NL; i++) {
        const float* tin = (i == 0) ? query : tgt;
        const float* W   = in_proj_w + (size_t)i * 3 * DDIM * DDIM;
        const float* Bb  = in_proj_b + (size_t)i * 3 * DDIM;

        // q = (tgt @ Wq^T + bq) * scaling ; k,v projections
        gemm_tb(ROWS_T, DDIM, DDIM, tin,      DDIM, 0, W,                 DDIM, 0,
                Bb,            SCALING, nullptr, 0, 0, q, DDIM, 0, 1);
        gemm_tb(ROWS_S, DDIM, DDIM, key_in,   DDIM, 0, W +     DDIM*DDIM, DDIM, 0,
                Bb + DDIM,     1.f,     nullptr, 0, 0, k, DDIM, 0, 1);
        gemm_tb(ROWS_S, DDIM, DDIM, value_in, DDIM, 0, W + 2 * DDIM*DDIM, DDIM, 0,
                Bb + 2 * DDIM, 1.f,     nullptr, 0, 0, v, DDIM, 0, 1);

        // scores[n,h,l,s] = q . k  (batched over z=n*H+h; view offset = z*64)
        gemm_tb(LLQ, SS, HDIM, q, NB * DDIM, 64, k, NB * DDIM, 64,
                nullptr, 1.f, nullptr, 0, 0, w, SS, (long long)LLQ * SS, NB * HH);

        softmax_kernel<<<NB * HH * LLQ, 256>>>(w, wpad);

        if (i == NL - 1)
            attnmap_kernel<<<((long long)NB * LLQ * SS + 255) / 256, 256>>>(
                w, out + (size_t)ROWS_T * DDIM);

        // attn[l,n,h,d] = sum_s w * v  (+ noise pad row added next)
        gemm_nb64(LLQ, HDIM, SS, w, SS, (long long)LLQ * SS,
                  v, NB * DDIM, 64, attn, NB * DDIM, 64, NB * HH);
        addnoise_kernel<<<((long long)ROWS_T * DDIM + 255) / 256, 256>>>(
            attn, wpad, noise + (size_t)i * NB * HH * HDIM);

        // out-proj + residual -> LN1
        gemm_tb(ROWS_T, DDIM, DDIM, attn, DDIM, 0, out_w + (size_t)i * DDIM * DDIM,
                DDIM, 0, out_b + i * DDIM, 1.f, tin, DDIM, 0, x1, DDIM, 0, 1);
        ln_kernel<<<ROWS_T, 256>>>(x1, ln1_g + i * DDIM, ln1_b + i * DDIM, x);

        // FFN
        gemm_tb(ROWS_T, FFD, DDIM, x, DDIM, 0, ff1_w + (size_t)i * FFD * DDIM,
                DDIM, 0, ff1_b + i * FFD, 1.f, nullptr, 0, 1, hbuf, FFD, 0, 1);
        gemm_tb(ROWS_T, DDIM, FFD, hbuf, FFD, 0, ff2_w + (size_t)i * DDIM * FFD,
                FFD, 0, ff2_b + i * DDIM, 1.f, x, DDIM, 0, y, DDIM, 0, 1);

        float* dst = (i == NL - 1) ? out : tgt;
        ln_kernel<<<ROWS_T, 256>>>(y, ln2_g + i * DDIM, ln2_b + i * DDIM, dst);
    }
}

// round 11
// speedup vs baseline: 3.2566x; 1.1166x over previous
#include <cuda_runtime.h>
#include <cstdint>
#include <math.h>

// ---------------- problem constants ----------------
#define NL   2
#define DDIM 1024
#define HH   16
#define HDIM 64
#define FFD  4096
#define SS   1024
#define NB   2
#define LLQ  4096
#define ROWS_T (LLQ*NB)   // 8192 query rows
#define ROWS_S (SS*NB)    // 2048 kv rows
#define SCALING 0.125f    // HD^-0.5

// ---------------- device scratch (static, allocation-free) ----------------
__device__ float g_q   [ROWS_T*DDIM];
__device__ float g_k   [ROWS_S*DDIM];
__device__ float g_v   [ROWS_S*DDIM];
__device__ float g_w   [134217728];      // NB*HH*LLQ*SS attention weights (512MB)
__device__ float g_wpad[NB*HH*LLQ];
__device__ float g_attn[ROWS_T*DDIM];
__device__ float g_x1  [ROWS_T*DDIM];
__device__ float g_x   [ROWS_T*DDIM];
__device__ float g_h   [ROWS_T*FFD];
__device__ float g_y   [ROWS_T*DDIM];
__device__ float g_tgt [ROWS_T*DDIM];
__device__ float g_noise[NL*NB*HH*HDIM];
// pre-rounded (tf32) copies
__device__ float g_ipw [NL*3*DDIM*DDIM];
__device__ float g_oww [NL*DDIM*DDIM];
__device__ float g_f1w [NL*FFD*DDIM];
__device__ float g_f2w [NL*DDIM*FFD];
__device__ float g_keyr[ROWS_S*DDIM];
__device__ float g_valr[ROWS_S*DDIM];
__device__ float g_qryr[ROWS_T*DDIM];
__device__ float g_xr  [ROWS_T*DDIM];
__device__ float g_tgtr[ROWS_T*DDIM];

// ---------------- TF32 rounding ----------------
__device__ __forceinline__ float tf32r(float x) {
    asm("cvt.rna.tf32.f32 %0, %0;" : "+f"(x));
    return x;
}

__global__ void round_copy(const float4* __restrict__ in, float4* __restrict__ out,
                           int n4) {
    int i = blockIdx.x * blockDim.x + threadIdx.x;
    if (i >= n4) return;
    float4 t = in[i];
    t.x = tf32r(t.x); t.y = tf32r(t.y); t.z = tf32r(t.z); t.w = tf32r(t.w);
    out[i] = t;
}

// ---------------- cp.async helpers ----------------
__device__ __forceinline__ void cp16(void* s, const void* g) {
    uint32_t sa = (uint32_t)__cvta_generic_to_shared(s);
    asm volatile("cp.async.cg.shared.global [%0], [%1], 16;" :: "r"(sa), "l"(g));
}
__device__ __forceinline__ void cp_commit() {
    asm volatile("cp.async.commit_group;");
}
template<int N>
__device__ __forceinline__ void cp_wait() {
    asm volatile("cp.async.wait_group %0;" :: "n"(N));
}

// ---------------- ldmatrix (tf32 fragments via b16 tiles) ----------------
__device__ __forceinline__ void ldsm4(uint32_t& r0, uint32_t& r1,
                                      uint32_t& r2, uint32_t& r3, uint32_t addr) {
    asm volatile("ldmatrix.sync.aligned.m8n8.x4.shared.b16 {%0,%1,%2,%3}, [%4];"
                 : "=r"(r0), "=r"(r1), "=r"(r2), "=r"(r3) : "r"(addr));
}

// ---------------- JAX threefry2x32 (partitionable) ----------------
__device__ __forceinline__ uint32_t rotl32(uint32_t x, int d) {
    return (x << d) | (x >> (32 - d));
}
__device__ __forceinline__ void threefry2x32(uint32_t k0, uint32_t k1,
                                             uint32_t& x0, uint32_t& x1) {
    uint32_t ks2 = k0 ^ k1 ^ 0x1BD11BDAu;
    x0 += k0; x1 += k1;
#define TFR(r) { x0 += x1; x1 = rotl32(x1, (r)); x1 ^= x0; }
    TFR(13) TFR(15) TFR(26) TFR(6)
    x0 += k1; x1 += ks2 + 1u;
    TFR(17) TFR(29) TFR(16) TFR(24)
    x0 += ks2; x1 += k0 + 2u;
    TFR(13) TFR(15) TFR(26) TFR(6)
    x0 += k0; x1 += k1 + 3u;
    TFR(17) TFR(29) TFR(16) TFR(24)
    x0 += k1; x1 += ks2 + 4u;
    TFR(13) TFR(15) TFR(26) TFR(6)
    x0 += ks2; x1 += k0 + 5u;
#undef TFR
}
__device__ __forceinline__ float bits_to_normal(uint32_t b) {
    float f = __uint_as_float((b >> 9) | 0x3F800000u) - 1.0f;   // [0,1)
    const float lo = -0.99999994f;
    float u = fmaxf(lo, f * 2.0f + lo);
    return 1.4142135623730951f * erfinvf(u);
}
__global__ void noise_kernel(float* __restrict__ noise) {
    int j = blockIdx.x * blockDim.x + threadIdx.x;
    if (j >= NL * 2048) return;
    int layer = j / 2048, jj = j % 2048;
    uint32_t k0 = 0u, k1 = 42u, x0 = 0u, x1 = (uint32_t)layer;
    threefry2x32(k0, k1, x0, x1);
    uint32_t b0 = 0u, b1 = (uint32_t)jj;
    threefry2x32(x0, x1, b0, b1);
    noise[layer * 2048 + jj] = bits_to_normal(b0 ^ b1);
}

// ---------------- TF32 tensor-core GEMM (mma.sync.m16n8k8) ----------------
__device__ __forceinline__ void mma_tf32(float* d, const uint32_t* a, const uint32_t* b) {
    asm volatile(
        "mma.sync.aligned.m16n8k8.row.col.f32.tf32.tf32.f32 "
        "{%0,%1,%2,%3}, {%4,%5,%6,%7}, {%8,%9}, {%0,%1,%2,%3};\n"
        : "+f"(d[0]), "+f"(d[1]), "+f"(d[2]), "+f"(d[3])
        : "r"(a[0]), "r"(a[1]), "r"(a[2]), "r"(a[3]), "r"(b[0]), "r"(b[1]));
}

// All GEMM inputs are pre-rounded to tf32; no cvt in the mainloop.
// A fragments and trans-B fragments via ldmatrix (b16 tiles == tf32 frags).
// roundc: round outputs to tf32 in the epilogue (for tensors feeding GEMMs).
template<int BM, int BN, int WM, int WN, bool TRANSB>
__global__ __launch_bounds__(256, 2)
void mma_gemm(int M, int Nn, int K,
              const float* __restrict__ A, int lda, long long sA,
              const float* __restrict__ B, int ldb, long long sB,
              const float* __restrict__ bias, float alpha,
              const float* __restrict__ resid, int ldr, int relu, int roundc,
              float* __restrict__ C, int ldc, long long sC)
{
    constexpr int BK = 32;
    constexpr int SA  = BK + 4;                     // 36 floats (144B rows)
    constexpr int SBT = BK + 4;
    constexpr int SBN = BN + 8;
    constexpr int ASTG = BM * SA;
    constexpr int BSTG = TRANSB ? (BN * SBT) : (BK * SBN);

    extern __shared__ __align__(16) float smem[];
    float* As = smem;
    float* Bs = smem + 2 * ASTG;

    long long bz = blockIdx.z;
    A += bz * sA; B += bz * sB; C += bz * sC;
    const int bm = blockIdx.y * BM;
    const int bn = blockIdx.x * BN;
    const int tid = threadIdx.x;
    const int wid = tid >> 5, lane = tid & 31;
    const int g = lane >> 2, tq = lane & 3;
    constexpr int WX = BN / WN;
    const int wm = (wid / WX) * WM, wn = (wid % WX) * WN;
    constexpr int MA = WM / 16, NA = WN / 8;

    float acc[MA][NA][4];
#pragma unroll
    for (int i = 0; i < MA; i++)
#pragma unroll
        for (int j = 0; j < NA; j++)
#pragma unroll
            for (int e = 0; e < 4; e++) acc[i][j][e] = 0.f;

    // ldmatrix lane address bases (bytes within a stage)
    const int ltile = lane >> 3, lr = lane & 7;
    const uint32_t s_base = (uint32_t)__cvta_generic_to_shared(smem);
    uint32_t baseA[MA];
#pragma unroll
    for (int ma = 0; ma < MA; ma++)
        baseA[ma] = ((wm + ma * 16 + (ltile & 1) * 8 + lr) * SA
                     + (ltile >> 1) * 4) * 4;
    uint32_t baseB[(NA + 1) / 2];
    if (TRANSB) {
#pragma unroll
        for (int p = 0; p < NA / 2; p++)
            baseB[p] = ((wn + p * 16 + (ltile >> 1) * 8 + lr) * SBT
                        + (ltile & 1) * 4) * 4;
    }

    auto load_tiles = [&](int st, int k0) {
        float* as = As + st * ASTG;
        float* bs = Bs + st * BSTG;
#pragma unroll
        for (int it = 0; it < BM * BK / (4 * 256); it++) {
            int vi = tid + it * 256;
            int r  = vi >> 3;
            int kc = (vi & 7) * 4;
            cp16(&as[r * SA + kc], A + (long long)(bm + r) * lda + k0 + kc);
        }
        if (TRANSB) {
#pragma unroll
            for (int it = 0; it < BN * BK / (4 * 256); it++) {
                int vi = tid + it * 256;
                int r  = vi >> 3;
                int kc = (vi & 7) * 4;
                cp16(&bs[r * SBT + kc], B + (long long)(bn + r) * ldb + k0 + kc);
            }
        } else {
#pragma unroll
            for (int it = 0; it < BK * BN / (4 * 256); it++) {
                int vi = tid + it * 256;
                int kk = vi / (BN / 4);
                int c  = (vi % (BN / 4)) * 4;
                cp16(&bs[kk * SBN + c], B + (long long)(k0 + kk) * ldb + bn + c);
            }
        }
    };

    const int nk = K / BK;
    load_tiles(0, 0);
    cp_commit();

    for (int i = 0; i < nk; i++) {
        const int buf = i & 1;
        if (i + 1 < nk) {
            load_tiles(buf ^ 1, (i + 1) * BK);
            cp_commit();
            cp_wait<1>();
        } else {
            cp_wait<0>();
        }
        __syncthreads();

        const uint32_t s_as = s_base + buf * ASTG * 4;
        const uint32_t s_bs = s_base + (2 * ASTG + buf * BSTG) * 4;
        const uint32_t* ub = reinterpret_cast<const uint32_t*>(Bs + buf * BSTG);

#pragma unroll
        for (int ka = 0; ka < BK / 8; ka++) {
            const int kb = ka * 8;
            uint32_t af[MA][4];
            uint32_t bf[NA][2];
#pragma unroll
            for (int ma = 0; ma < MA; ma++)
                ldsm4(af[ma][0], af[ma][1], af[ma][2], af[ma][3],
                      s_as + baseA[ma] + kb * 4);
            if (TRANSB) {
#pragma unroll
                for (int p = 0; p < NA / 2; p++)
                    ldsm4(bf[2 * p][0], bf[2 * p][1], bf[2 * p + 1][0],
                          bf[2 * p + 1][1], s_bs + baseB[p] + kb * 4);
            } else {
#pragma unroll
                for (int na = 0; na < NA; na++) {
                    int nc = wn + na * 8 + g;
                    bf[na][0] = ub[(kb + tq) * SBN + nc];
                    bf[na][1] = ub[(kb + tq + 4) * SBN + nc];
                }
            }
#pragma unroll
            for (int ma = 0; ma < MA; ma++)
#pragma unroll
                for (int na = 0; na < NA; na++)
                    mma_tf32(acc[ma][na], af[ma], bf[na]);
        }
        __syncthreads();
    }

    // ---- epilogue ----
#pragma unroll
    for (int ma = 0; ma < MA; ma++) {
#pragma unroll
        for (int na = 0; na < NA; na++) {
            int c0 = bn + wn + na * 8 + tq * 2;
#pragma unroll
            for (int hh = 0; hh < 2; hh++) {
                long long rr = bm + wm + ma * 16 + g + hh * 8;
                float v0 = acc[ma][na][hh * 2 + 0];
                float v1 = acc[ma][na][hh * 2 + 1];
                if (bias) { v0 += bias[c0]; v1 += bias[c0 + 1]; }
                v0 *= alpha; v1 *= alpha;
                if (resid) {
                    float2 rv = *reinterpret_cast<const float2*>(
                        resid + rr * (long long)ldr + c0);
                    v0 += rv.x; v1 += rv.y;
                }
                if (relu) { v0 = fmaxf(v0, 0.f); v1 = fmaxf(v1, 0.f); }
                if (roundc) { v0 = tf32r(v0); v1 = tf32r(v1); }
                *reinterpret_cast<float2*>(C + rr * (long long)ldc + c0) =
                    make_float2(v0, v1);
            }
        }
    }
}

// ---------------- softmax over S=1024 (+ implicit zero pad column) ----------------
// Stores tf32-rounded weights (they feed the attnV GEMM).
__global__ void softmax_kernel(float* __restrict__ w, float* __restrict__ wpad) {
    long long row = blockIdx.x;
    float4* p = reinterpret_cast<float4*>(w + row * (long long)SS);
    int t = threadIdx.x;
    float4 v = p[t];
    __shared__ float red[256];
    float m = fmaxf(fmaxf(v.x, v.y), fmaxf(v.z, v.w));
    red[t] = m; __syncthreads();
    for (int o = 128; o > 0; o >>= 1) {
        if (t < o) red[t] = fmaxf(red[t], red[t + o]);
        __syncthreads();
    }
    m = fmaxf(red[0], 0.f);
    __syncthreads();
    v.x = expf(v.x - m); v.y = expf(v.y - m);
    v.z = expf(v.z - m); v.w = expf(v.w - m);
    red[t] = v.x + v.y + v.z + v.w; __syncthreads();
    for (int o = 128; o > 0; o >>= 1) {
        if (t < o) red[t] += red[t + o];
        __syncthreads();
    }
    float epad = expf(-m);
    float inv = 1.f / (red[0] + epad);
    v.x = tf32r(v.x * inv); v.y = tf32r(v.y * inv);
    v.z = tf32r(v.z * inv); v.w = tf32r(v.w * inv);
    p[t] = v;
    if (t == 0) wpad[row] = epad * inv;
}

// ---------------- layernorm over D=1024; optional tf32-rounded copy ----------------
__global__ void ln_kernel(const float* __restrict__ x, const float* __restrict__ g,
                          const float* __restrict__ b, float* __restrict__ y,
                          float* __restrict__ yr) {
    long long row = blockIdx.x;
    const float4* px = reinterpret_cast<const float4*>(x + row * (long long)DDIM);
    int t = threadIdx.x;
    float4 v = px[t];
    __shared__ float r1[256], r2[256];
    r1[t] = v.x + v.y + v.z + v.w;
    r2[t] = v.x*v.x + v.y*v.y + v.z*v.z + v.w*v.w;
    __syncthreads();
    for (int o = 128; o > 0; o >>= 1) {
        if (t < o) { r1[t] += r1[t + o]; r2[t] += r2[t + o]; }
        __syncthreads();
    }
    float mu  = r1[0] * (1.f / DDIM);
    float var = r2[0] * (1.f / DDIM) - mu * mu;
    float rs  = rsqrtf(var + 1e-5f);
    float4 gg = reinterpret_cast<const float4*>(g)[t];
    float4 bb = reinterpret_cast<const float4*>(b)[t];
    float4 o4;
    o4.x = (v.x - mu) * rs * gg.x + bb.x;
    o4.y = (v.y - mu) * rs * gg.y + bb.y;
    o4.z = (v.z - mu) * rs * gg.z + bb.z;
    o4.w = (v.w - mu) * rs * gg.w + bb.w;
    reinterpret_cast<float4*>(y + row * (long long)DDIM)[t] = o4;
    if (yr) {
        float4 q4;
        q4.x = tf32r(o4.x); q4.y = tf32r(o4.y);
        q4.z = tf32r(o4.z); q4.w = tf32r(o4.w);
        reinterpret_cast<float4*>(yr + row * (long long)DDIM)[t] = q4;
    }
}

// ---------------- attn_map = mean_h sigmoid(w) ----------------
__global__ void attnmap_kernel(const float* __restrict__ w, float* __restrict__ out) {
    long long idx = (long long)blockIdx.x * blockDim.x + threadIdx.x;
    if (idx >= (long long)NB * LLQ * SS) return;
    int s = (int)(idx & (SS - 1));
    long long t2 = idx >> 10;
    int l = (int)(t2 & (LLQ - 1));
    int n = (int)(t2 >> 12);
    float acc = 0.f;
#pragma unroll
    for (int h = 0; h < HH; h++) {
        float v = w[(((long long)(n * HH + h) * LLQ + l) << 10) + s];
        acc += 1.f / (1.f + expf(-v));
    }
    out[idx] = acc * (1.f / HH);
}

// ---------------- add pad noise; round attn (it feeds out-proj GEMM) ----------------
__global__ void addnoise_kernel(float* __restrict__ attn,
                                const float* __restrict__ wpad,
                                const float* __restrict__ noise) {
    long long idx = (long long)blockIdx.x * blockDim.x + threadIdx.x;
    if (idx >= (long long)ROWS_T * DDIM) return;
    int c = (int)(idx & 1023);
    long long r = idx >> 10;
    int n = (int)(r & 1);
    int l = (int)(r >> 1);
    int h = c >> 6, d = c & 63;
    float s = attn[idx] + tf32r(wpad[(n * HH + h) * LLQ + l]) *
                          tf32r(noise[(n * HH + h) * HDIM + d]);
    attn[idx] = tf32r(s);
}

// ---------------- host launchers ----------------
static const int SMEM_TB  = 2 * (128 * 36 + 128 * 36) * 4;   // 73728 B
static const int SMEM_NB  = 2 * (128 * 36 + 32 * 72) * 4;    // 55296 B

static void gemm_tb(int M, int Nn, int K,
                    const float* A, int lda, long long sA,
                    const float* B, int ldb, long long sB,
                    const float* bias, float alpha,
                    const float* resid, int ldr, int relu, int roundc,
                    float* C, int ldc, long long sC, int batch) {
    cudaFuncSetAttribute(mma_gemm<128, 128, 64, 32, true>,
                         cudaFuncAttributeMaxDynamicSharedMemorySize, SMEM_TB);
    dim3 grid(Nn / 128, M / 128, batch), blk(256);
    mma_gemm<128, 128, 64, 32, true><<<grid, blk, SMEM_TB>>>(
        M, Nn, K, A, lda, sA, B, ldb, sB, bias, alpha, resid, ldr, relu, roundc,
        C, ldc, sC);
}
static void gemm_nb64(int M, int Nn, int K,
                      const float* A, int lda, long long sA,
                      const float* B, int ldb, long long sB,
                      float* C, int ldc, long long sC, int batch) {
    cudaFuncSetAttribute(mma_gemm<128, 64, 64, 16, false>,
                         cudaFuncAttributeMaxDynamicSharedMemorySize, SMEM_NB);
    dim3 grid(Nn / 64, M / 128, batch), blk(256);
    mma_gemm<128, 64, 64, 16, false><<<grid, blk, SMEM_NB>>>(
        M, Nn, K, A, lda, sA, B, ldb, sB, nullptr, 1.f, nullptr, 0, 0, 0,
        C, ldc, sC);
}
static void rcopy(const float* in, float* out, long long n) {
    int n4 = (int)(n / 4);
    round_copy<<<(n4 + 255) / 256, 256>>>(
        (const float4*)in, (float4*)out, n4);
}

extern "C" void kernel_launch(void* const* d_in, const int* in_sizes, int n_in,
                              void* d_out, int out_size) {
    const float* key_in    = (const float*)d_in[0];
    const float* value_in  = (const float*)d_in[1];
    const float* query     = (const float*)d_in[2];
    const float* in_proj_w = (const float*)d_in[3];
    const float* in_proj_b = (const float*)d_in[4];
    const float* out_w     = (const float*)d_in[5];
    const float* out_b     = (const float*)d_in[6];
    const float* ln1_g     = (const float*)d_in[7];
    const float* ln1_b     = (const float*)d_in[8];
    const float* ln2_g     = (const float*)d_in[9];
    const float* ln2_b     = (const float*)d_in[10];
    const float* ff1_w     = (const float*)d_in[11];
    const float* ff1_b     = (const float*)d_in[12];
    const float* ff2_w     = (const float*)d_in[13];
    const float* ff2_b     = (const float*)d_in[14];
    float* out = (float*)d_out;

    float *q, *k, *v, *w, *wpad, *attn, *x1, *x, *hbuf, *y, *tgt, *noise;
    float *ipw, *oww, *f1w, *f2w, *keyr, *valr, *qryr, *xr, *tgtr;
    cudaGetSymbolAddress((void**)&q,     g_q);
    cudaGetSymbolAddress((void**)&k,     g_k);
    cudaGetSymbolAddress((void**)&v,     g_v);
    cudaGetSymbolAddress((void**)&w,     g_w);
    cudaGetSymbolAddress((void**)&wpad,  g_wpad);
    cudaGetSymbolAddress((void**)&attn,  g_attn);
    cudaGetSymbolAddress((void**)&x1,    g_x1);
    cudaGetSymbolAddress((void**)&x,     g_x);
    cudaGetSymbolAddress((void**)&hbuf,  g_h);
    cudaGetSymbolAddress((void**)&y,     g_y);
    cudaGetSymbolAddress((void**)&tgt,   g_tgt);
    cudaGetSymbolAddress((void**)&noise, g_noise);
    cudaGetSymbolAddress((void**)&ipw,   g_ipw);
    cudaGetSymbolAddress((void**)&oww,   g_oww);
    cudaGetSymbolAddress((void**)&f1w,   g_f1w);
    cudaGetSymbolAddress((void**)&f2w,   g_f2w);
    cudaGetSymbolAddress((void**)&keyr,  g_keyr);
    cudaGetSymbolAddress((void**)&valr,  g_valr);
    cudaGetSymbolAddress((void**)&qryr,  g_qryr);
    cudaGetSymbolAddress((void**)&xr,    g_xr);
    cudaGetSymbolAddress((void**)&tgtr,  g_tgtr);

    // one-time tf32 pre-rounding of all GEMM operands coming from inputs
    rcopy(in_proj_w, ipw,  (long long)NL * 3 * DDIM * DDIM);
    rcopy(out_w,     oww,  (long long)NL * DDIM * DDIM);
    rcopy(ff1_w,     f1w,  (long long)NL * FFD * DDIM);
    rcopy(ff2_w,     f2w,  (long long)NL * DDIM * FFD);
    rcopy(key_in,    keyr, (long long)ROWS_S * DDIM);
    rcopy(value_in,  valr, (long long)ROWS_S * DDIM);
    rcopy(query,     qryr, (long long)ROWS_T * DDIM);

    noise_kernel<<<(NL * 2048 + 255) / 256, 256>>>(noise);

    for (int i = 0; i < NL; i++) {
        const float* tinr = (i == 0) ? qryr : tgtr;   // rounded (GEMM A)
        const float* tine = (i == 0) ? query : tgt;   // exact (residual)
        const float* W    = ipw + (size_t)i * 3 * DDIM * DDIM;
        const float* Bb   = in_proj_b + (size_t)i * 3 * DDIM;

        // q/k/v projections; outputs rounded (they feed the attention GEMMs)
        gemm_tb(ROWS_T, DDIM, DDIM, tinr, DDIM, 0, W,                 DDIM, 0,
                Bb,            SCALING, nullptr, 0, 0, 1, q, DDIM, 0, 1);
        gemm_tb(ROWS_S, DDIM, DDIM, keyr, DDIM, 0, W +     DDIM*DDIM, DDIM, 0,
                Bb + DDIM,     1.f,     nullptr, 0, 0, 1, k, DDIM, 0, 1);
        gemm_tb(ROWS_S, DDIM, DDIM, valr, DDIM, 0, W + 2 * DDIM*DDIM, DDIM, 0,
                Bb + 2 * DDIM, 1.f,     nullptr, 0, 0, 1, v, DDIM, 0, 1);

        // scores (exact output -> softmax)
        gemm_tb(LLQ, SS, HDIM, q, NB * DDIM, 64, k, NB * DDIM, 64,
                nullptr, 1.f, nullptr, 0, 0, 0, w, SS, (long long)LLQ * SS, NB * HH);

        softmax_kernel<<<NB * HH * LLQ, 256>>>(w, wpad);

        if (i == NL - 1)
            attnmap_kernel<<<((long long)NB * LLQ * SS + 255) / 256, 256>>>(
                w, out + (size_t)ROWS_T * DDIM);

        gemm_nb64(LLQ, HDIM, SS, w, SS, (long long)LLQ * SS,
                  v, NB * DDIM, 64, attn, NB * DDIM, 64, NB * HH);
        addnoise_kernel<<<((long long)ROWS_T * DDIM + 255) / 256, 256>>>(
            attn, wpad, noise + (size_t)i * NB * HH * HDIM);

        // out-proj + residual -> LN1 (x exact + xr rounded)
        gemm_tb(ROWS_T, DDIM, DDIM, attn, DDIM, 0, oww + (size_t)i * DDIM * DDIM,
                DDIM, 0, out_b + i * DDIM, 1.f, tine, DDIM, 0, 0, x1, DDIM, 0, 1);
        ln_kernel<<<ROWS_T, 256>>>(x1, ln1_g + i * DDIM, ln1_b + i * DDIM, x, xr);

        // FFN: h rounded (feeds ff2); y exact -> LN2
        gemm_tb(ROWS_T, FFD, DDIM, xr, DDIM, 0, f1w + (size_t)i * FFD * DDIM,
                DDIM, 0, ff1_b + i * FFD, 1.f, nullptr, 0, 1, 1, hbuf, FFD, 0, 1);
        gemm_tb(ROWS_T, DDIM, FFD, hbuf, FFD, 0, f2w + (size_t)i * DDIM * FFD,
                FFD, 0, ff2_b + i * DDIM, 1.f, x, DDIM, 0, 0, y, DDIM, 0, 1);

        if (i == NL - 1)
            ln_kernel<<<ROWS_T, 256>>>(y, ln2_g + i * DDIM, ln2_b + i * DDIM,
                                       out, nullptr);
        else
            ln_kernel<<<ROWS_T, 256>>>(y, ln2_g + i * DDIM, ln2_b + i * DDIM,
                                       tgt, tgtr);
    }
}

// round 12
// speedup vs baseline: 3.5101x; 1.0778x over previous
#include <cuda_runtime.h>
#include <cstdint>
#include <math.h>

// ---------------- problem constants ----------------
#define NL   2
#define DDIM 1024
#define HH   16
#define HDIM 64
#define FFD  4096
#define SS   1024
#define NB   2
#define LLQ  4096
#define ROWS_T (LLQ*NB)   // 8192 query rows
#define ROWS_S (SS*NB)    // 2048 kv rows
#define SCALING 0.125f    // HD^-0.5

// ---------------- device scratch (static, allocation-free) ----------------
__device__ float g_q   [ROWS_T*DDIM];
__device__ float g_k   [ROWS_S*DDIM];
__device__ float g_v   [ROWS_S*DDIM];
__device__ float g_attn[ROWS_T*DDIM];
__device__ float g_x1  [ROWS_T*DDIM];
__device__ float g_x   [ROWS_T*DDIM];
__device__ float g_h   [ROWS_T*FFD];
__device__ float g_y   [ROWS_T*DDIM];
__device__ float g_tgt [ROWS_T*DDIM];
__device__ float g_noise[NL*NB*HH*HDIM];
__device__ float g_m   [NB*HH*LLQ];     // per-row softmax max (incl pad 0)
__device__ float g_zi  [NB*HH*LLQ];     // per-row 1/Z
// pre-rounded (tf32) copies
__device__ float g_ipw [NL*3*DDIM*DDIM];
__device__ float g_oww [NL*DDIM*DDIM];
__device__ float g_f1w [NL*FFD*DDIM];
__device__ float g_f2w [NL*DDIM*FFD];
__device__ float g_keyr[ROWS_S*DDIM];
__device__ float g_valr[ROWS_S*DDIM];
__device__ float g_qryr[ROWS_T*DDIM];
__device__ float g_xr  [ROWS_T*DDIM];
__device__ float g_tgtr[ROWS_T*DDIM];

// ---------------- TF32 rounding ----------------
__device__ __forceinline__ float tf32r(float x) {
    asm("cvt.rna.tf32.f32 %0, %0;" : "+f"(x));
    return x;
}

__global__ void round_copy(const float4* __restrict__ in, float4* __restrict__ out,
                           int n4) {
    int i = blockIdx.x * blockDim.x + threadIdx.x;
    if (i >= n4) return;
    float4 t = in[i];
    t.x = tf32r(t.x); t.y = tf32r(t.y); t.z = tf32r(t.z); t.w = tf32r(t.w);
    out[i] = t;
}

// ---------------- cp.async helpers ----------------
__device__ __forceinline__ void cp16(void* s, const void* g) {
    uint32_t sa = (uint32_t)__cvta_generic_to_shared(s);
    asm volatile("cp.async.cg.shared.global [%0], [%1], 16;" :: "r"(sa), "l"(g));
}
__device__ __forceinline__ void cp_commit() {
    asm volatile("cp.async.commit_group;");
}
template<int N>
__device__ __forceinline__ void cp_wait() {
    asm volatile("cp.async.wait_group %0;" :: "n"(N));
}

// ---------------- ldmatrix (tf32 fragments via b16 tiles) ----------------
__device__ __forceinline__ void ldsm4(uint32_t& r0, uint32_t& r1,
                                      uint32_t& r2, uint32_t& r3, uint32_t addr) {
    asm volatile("ldmatrix.sync.aligned.m8n8.x4.shared.b16 {%0,%1,%2,%3}, [%4];"
                 : "=r"(r0), "=r"(r1), "=r"(r2), "=r"(r3) : "r"(addr));
}

// ---------------- JAX threefry2x32 (partitionable) ----------------
__device__ __forceinline__ uint32_t rotl32(uint32_t x, int d) {
    return (x << d) | (x >> (32 - d));
}
__device__ __forceinline__ void threefry2x32(uint32_t k0, uint32_t k1,
                                             uint32_t& x0, uint32_t& x1) {
    uint32_t ks2 = k0 ^ k1 ^ 0x1BD11BDAu;
    x0 += k0; x1 += k1;
#define TFR(r) { x0 += x1; x1 = rotl32(x1, (r)); x1 ^= x0; }
    TFR(13) TFR(15) TFR(26) TFR(6)
    x0 += k1; x1 += ks2 + 1u;
    TFR(17) TFR(29) TFR(16) TFR(24)
    x0 += ks2; x1 += k0 + 2u;
    TFR(13) TFR(15) TFR(26) TFR(6)
    x0 += k0; x1 += k1 + 3u;
    TFR(17) TFR(29) TFR(16) TFR(24)
    x0 += k1; x1 += ks2 + 4u;
    TFR(13) TFR(15) TFR(26) TFR(6)
    x0 += ks2; x1 += k0 + 5u;
#undef TFR
}
__device__ __forceinline__ float bits_to_normal(uint32_t b) {
    float f = __uint_as_float((b >> 9) | 0x3F800000u) - 1.0f;   // [0,1)
    const float lo = -0.99999994f;
    float u = fmaxf(lo, f * 2.0f + lo);
    return 1.4142135623730951f * erfinvf(u);
}
__global__ void noise_kernel(float* __restrict__ noise) {
    int j = blockIdx.x * blockDim.x + threadIdx.x;
    if (j >= NL * 2048) return;
    int layer = j / 2048, jj = j % 2048;
    uint32_t k0 = 0u, k1 = 42u, x0 = 0u, x1 = (uint32_t)layer;
    threefry2x32(k0, k1, x0, x1);
    uint32_t b0 = 0u, b1 = (uint32_t)jj;
    threefry2x32(x0, x1, b0, b1);
    noise[layer * 2048 + jj] = bits_to_normal(b0 ^ b1);
}

// ---------------- TF32 tensor-core GEMM (mma.sync.m16n8k8) ----------------
__device__ __forceinline__ void mma_tf32(float* d, const uint32_t* a, const uint32_t* b) {
    asm volatile(
        "mma.sync.aligned.m16n8k8.row.col.f32.tf32.tf32.f32 "
        "{%0,%1,%2,%3}, {%4,%5,%6,%7}, {%8,%9}, {%0,%1,%2,%3};\n"
        : "+f"(d[0]), "+f"(d[1]), "+f"(d[2]), "+f"(d[3])
        : "r"(a[0]), "r"(a[1]), "r"(a[2]), "r"(a[3]), "r"(b[0]), "r"(b[1]));
}

// ================= generic GEMM (projections / FFN), unchanged =================
template<int BM, int BN, int WM, int WN, bool TRANSB>
__global__ __launch_bounds__(256, 2)
void mma_gemm(int M, int Nn, int K,
              const float* __restrict__ A, int lda, long long sA,
              const float* __restrict__ B, int ldb, long long sB,
              const float* __restrict__ bias, float alpha,
              const float* __restrict__ resid, int ldr, int relu, int roundc,
              float* __restrict__ C, int ldc, long long sC)
{
    constexpr int BK = 32;
    constexpr int SA  = BK + 4;
    constexpr int SBT = BK + 4;
    constexpr int SBN = BN + 8;
    constexpr int ASTG = BM * SA;
    constexpr int BSTG = TRANSB ? (BN * SBT) : (BK * SBN);

    extern __shared__ __align__(16) float smem[];
    float* As = smem;
    float* Bs = smem + 2 * ASTG;

    long long bz = blockIdx.z;
    A += bz * sA; B += bz * sB; C += bz * sC;
    const int bm = blockIdx.y * BM;
    const int bn = blockIdx.x * BN;
    const int tid = threadIdx.x;
    const int wid = tid >> 5, lane = tid & 31;
    const int g = lane >> 2, tq = lane & 3;
    constexpr int WX = BN / WN;
    const int wm = (wid / WX) * WM, wn = (wid % WX) * WN;
    constexpr int MA = WM / 16, NA = WN / 8;

    float acc[MA][NA][4];
#pragma unroll
    for (int i = 0; i < MA; i++)
#pragma unroll
        for (int j = 0; j < NA; j++)
#pragma unroll
            for (int e = 0; e < 4; e++) acc[i][j][e] = 0.f;

    const int ltile = lane >> 3, lr = lane & 7;
    const uint32_t s_base = (uint32_t)__cvta_generic_to_shared(smem);
    uint32_t baseA[MA];
#pragma unroll
    for (int ma = 0; ma < MA; ma++)
        baseA[ma] = ((wm + ma * 16 + (ltile & 1) * 8 + lr) * SA
                     + (ltile >> 1) * 4) * 4;
    uint32_t baseB[(NA + 1) / 2];
    if (TRANSB) {
#pragma unroll
        for (int p = 0; p < NA / 2; p++)
            baseB[p] = ((wn + p * 16 + (ltile >> 1) * 8 + lr) * SBT
                        + (ltile & 1) * 4) * 4;
    }

    auto load_tiles = [&](int st, int k0) {
        float* as = As + st * ASTG;
        float* bs = Bs + st * BSTG;
#pragma unroll
        for (int it = 0; it < BM * BK / (4 * 256); it++) {
            int vi = tid + it * 256;
            int r  = vi >> 3;
            int kc = (vi & 7) * 4;
            cp16(&as[r * SA + kc], A + (long long)(bm + r) * lda + k0 + kc);
        }
        if (TRANSB) {
#pragma unroll
            for (int it = 0; it < BN * BK / (4 * 256); it++) {
                int vi = tid + it * 256;
                int r  = vi >> 3;
                int kc = (vi & 7) * 4;
                cp16(&bs[r * SBT + kc], B + (long long)(bn + r) * ldb + k0 + kc);
            }
        } else {
#pragma unroll
            for (int it = 0; it < BK * BN / (4 * 256); it++) {
                int vi = tid + it * 256;
                int kk = vi / (BN / 4);
                int c  = (vi % (BN / 4)) * 4;
                cp16(&bs[kk * SBN + c], B + (long long)(k0 + kk) * ldb + bn + c);
            }
        }
    };

    const int nk = K / BK;
    load_tiles(0, 0);
    cp_commit();

    for (int i = 0; i < nk; i++) {
        const int buf = i & 1;
        if (i + 1 < nk) {
            load_tiles(buf ^ 1, (i + 1) * BK);
            cp_commit();
            cp_wait<1>();
        } else {
            cp_wait<0>();
        }
        __syncthreads();

        const uint32_t s_as = s_base + buf * ASTG * 4;
        const uint32_t s_bs = s_base + (2 * ASTG + buf * BSTG) * 4;
        const uint32_t* ub = reinterpret_cast<const uint32_t*>(Bs + buf * BSTG);

#pragma unroll
        for (int ka = 0; ka < BK / 8; ka++) {
            const int kb = ka * 8;
            uint32_t af[MA][4];
            uint32_t bf[NA][2];
#pragma unroll
            for (int ma = 0; ma < MA; ma++)
                ldsm4(af[ma][0], af[ma][1], af[ma][2], af[ma][3],
                      s_as + baseA[ma] + kb * 4);
            if (TRANSB) {
#pragma unroll
                for (int p = 0; p < NA / 2; p++)
                    ldsm4(bf[2 * p][0], bf[2 * p][1], bf[2 * p + 1][0],
                          bf[2 * p + 1][1], s_bs + baseB[p] + kb * 4);
            } else {
#pragma unroll
                for (int na = 0; na < NA; na++) {
                    int nc = wn + na * 8 + g;
                    bf[na][0] = ub[(kb + tq) * SBN + nc];
                    bf[na][1] = ub[(kb + tq + 4) * SBN + nc];
                }
            }
#pragma unroll
            for (int ma = 0; ma < MA; ma++)
#pragma unroll
                for (int na = 0; na < NA; na++)
                    mma_tf32(acc[ma][na], af[ma], bf[na]);
        }
        __syncthreads();
    }

#pragma unroll
    for (int ma = 0; ma < MA; ma++) {
#pragma unroll
        for (int na = 0; na < NA; na++) {
            int c0 = bn + wn + na * 8 + tq * 2;
#pragma unroll
            for (int hh = 0; hh < 2; hh++) {
                long long rr = bm + wm + ma * 16 + g + hh * 8;
                float v0 = acc[ma][na][hh * 2 + 0];
                float v1 = acc[ma][na][hh * 2 + 1];
                if (bias) { v0 += bias[c0]; v1 += bias[c0 + 1]; }
                v0 *= alpha; v1 *= alpha;
                if (resid) {
                    float2 rv = *reinterpret_cast<const float2*>(
                        resid + rr * (long long)ldr + c0);
                    v0 += rv.x; v1 += rv.y;
                }
                if (relu) { v0 = fmaxf(v0, 0.f); v1 = fmaxf(v1, 0.f); }
                if (roundc) { v0 = tf32r(v0); v1 = tf32r(v1); }
                *reinterpret_cast<float2*>(C + rr * (long long)ldc + c0) =
                    make_float2(v0, v1);
            }
        }
    }
}

// ================= fused flash attention =================
// Per CTA: one z=(n,h), one 128-row l-tile. Loops 8 s-tiles of 128.
// smem floats: [K0|K1: 2*8704][V0|V1: 2*8704][P: 128*132=16896 (Q staged here)]
#define FKSTR 68
#define FPSTR 132
#define FKSTG (128*FKSTR)
#define FVOFF (2*FKSTG)
#define FPOFF (4*FKSTG)
#define FL_SMEM ((4*FKSTG + 128*FPSTR) * 4)   // 206848 B

__global__ void __launch_bounds__(256, 1)
flash_kernel(const float* __restrict__ q, const float* __restrict__ k,
             const float* __restrict__ v, const float* __restrict__ noise,
             float* __restrict__ attn, float* __restrict__ msav,
             float* __restrict__ zisav)
{
    extern __shared__ __align__(16) float sm[];
    const int z = blockIdx.y, lt = blockIdx.x;
    const int tid = threadIdx.x, wid = tid >> 5, lane = tid & 31;
    const int g = lane >> 2, tq = lane & 3;
    const int ltile = lane >> 3, lr = lane & 7;
    const int wr0 = wid * 16;
    const float* qz = q + z * 64;
    const float* kz = k + z * 64;
    const float* vz = v + z * 64;
    const uint32_t sbase = (uint32_t)__cvta_generic_to_shared(sm);

    // stage Q into P region; prefetch K0, V0 (one group each)
#pragma unroll
    for (int i = 0; i < 8; i++) {
        int vi = tid + i * 256; int r = vi >> 4; int c = (vi & 15) << 2;
        cp16(&sm[FPOFF + r * FKSTR + c], qz + (size_t)(lt * 128 + r) * 2048 + c);
    }
    cp_commit();
#pragma unroll
    for (int i = 0; i < 8; i++) {
        int vi = tid + i * 256; int r = vi >> 4; int c = (vi & 15) << 2;
        cp16(&sm[r * FKSTR + c], kz + (size_t)r * 2048 + c);
    }
    cp_commit();
#pragma unroll
    for (int i = 0; i < 8; i++) {
        int vi = tid + i * 256; int r = vi >> 4; int c = (vi & 15) << 2;
        cp16(&sm[FVOFF + r * FKSTR + c], vz + (size_t)r * 2048 + c);
    }
    cp_commit();

    cp_wait<2>(); __syncthreads();
    uint32_t qf[8][4];
    {
        uint32_t qaddr = sbase +
            (FPOFF + (wr0 + (ltile & 1) * 8 + lr) * FKSTR + (ltile >> 1) * 4) * 4;
#pragma unroll
        for (int ka = 0; ka < 8; ka++)
            ldsm4(qf[ka][0], qf[ka][1], qf[ka][2], qf[ka][3], qaddr + ka * 32);
    }
    __syncthreads();   // Q fragments captured; P region may be overwritten now

    uint32_t kaddr[8];
#pragma unroll
    for (int p = 0; p < 8; p++)
        kaddr[p] = sbase + ((p * 16 + (ltile >> 1) * 8 + lr) * FKSTR
                            + (ltile & 1) * 4) * 4;
    const uint32_t paddr = sbase +
        (FPOFF + (wr0 + (ltile & 1) * 8 + lr) * FPSTR + (ltile >> 1) * 4) * 4;

    float m0 = -1e30f, m1 = -1e30f, z0 = 0.f, z1 = 0.f;
    float oacc[8][4];
#pragma unroll
    for (int na = 0; na < 8; na++)
#pragma unroll
        for (int e = 0; e < 4; e++) oacc[na][e] = 0.f;

    for (int it = 0; it < 8; it++) {
        const int buf = it & 1;
        cp_wait<1>(); __syncthreads();          // K(it) ready; prev iter done

        // ---- S = Q K^T ----
        float sacc[16][4];
#pragma unroll
        for (int na = 0; na < 16; na++)
#pragma unroll
            for (int e = 0; e < 4; e++) sacc[na][e] = 0.f;
        const uint32_t kboff = (uint32_t)buf * FKSTG * 4;
#pragma unroll
        for (int ka = 0; ka < 8; ka++) {
            uint32_t kf[16][2];
#pragma unroll
            for (int p = 0; p < 8; p++)
                ldsm4(kf[2 * p][0], kf[2 * p][1], kf[2 * p + 1][0],
                      kf[2 * p + 1][1], kaddr[p] + kboff + ka * 32);
#pragma unroll
            for (int na = 0; na < 16; na++)
                mma_tf32(sacc[na], qf[ka], kf[na]);
        }

        // prefetch K(it+1)
        if (it < 7) {
            float* kd = sm + ((it + 1) & 1) * FKSTG;
#pragma unroll
            for (int i = 0; i < 8; i++) {
                int vi = tid + i * 256; int r = vi >> 4; int c = (vi & 15) << 2;
                cp16(&kd[r * FKSTR + c],
                     kz + (size_t)((it + 1) * 128 + r) * 2048 + c);
            }
            cp_commit();
        }

        // ---- online softmax ----
        float t0 = -1e30f, t1 = -1e30f;
#pragma unroll
        for (int na = 0; na < 16; na++) {
            t0 = fmaxf(t0, fmaxf(sacc[na][0], sacc[na][1]));
            t1 = fmaxf(t1, fmaxf(sacc[na][2], sacc[na][3]));
        }
        t0 = fmaxf(t0, __shfl_xor_sync(0xffffffffu, t0, 1));
        t0 = fmaxf(t0, __shfl_xor_sync(0xffffffffu, t0, 2));
        t1 = fmaxf(t1, __shfl_xor_sync(0xffffffffu, t1, 1));
        t1 = fmaxf(t1, __shfl_xor_sync(0xffffffffu, t1, 2));
        float mn0 = fmaxf(m0, t0), mn1 = fmaxf(m1, t1);
        float sc0 = expf(m0 - mn0), sc1 = expf(m1 - mn1);
        m0 = mn0; m1 = mn1;
        z0 *= sc0; z1 *= sc1;
#pragma unroll
        for (int na = 0; na < 8; na++) {
            oacc[na][0] *= sc0; oacc[na][1] *= sc0;
            oacc[na][2] *= sc1; oacc[na][3] *= sc1;
        }
        float s0 = 0.f, s1 = 0.f;
#pragma unroll
        for (int na = 0; na < 16; na++) {
            float p0 = expf(sacc[na][0] - mn0), p1 = expf(sacc[na][1] - mn0);
            float p2 = expf(sacc[na][2] - mn1), p3 = expf(sacc[na][3] - mn1);
            s0 += p0 + p1; s1 += p2 + p3;
            int c0 = na * 8 + tq * 2;
            *reinterpret_cast<float2*>(&sm[FPOFF + (wr0 + g) * FPSTR + c0]) =
                make_float2(tf32r(p0), tf32r(p1));
            *reinterpret_cast<float2*>(&sm[FPOFF + (wr0 + g + 8) * FPSTR + c0]) =
                make_float2(tf32r(p2), tf32r(p3));
        }
        s0 += __shfl_xor_sync(0xffffffffu, s0, 1);
        s0 += __shfl_xor_sync(0xffffffffu, s0, 2);
        s1 += __shfl_xor_sync(0xffffffffu, s1, 1);
        s1 += __shfl_xor_sync(0xffffffffu, s1, 2);
        z0 += s0; z1 += s1;

        if (it < 7) { cp_wait<1>(); } else { cp_wait<0>(); }   // V(it) ready
        __syncthreads();                                        // P written

        // ---- O += P V ----
        const uint32_t* vb =
            reinterpret_cast<const uint32_t*>(sm + FVOFF + buf * FKSTG);
#pragma unroll
        for (int ks = 0; ks < 16; ks++) {
            uint32_t pf[4];
            ldsm4(pf[0], pf[1], pf[2], pf[3], paddr + ks * 32);
#pragma unroll
            for (int na = 0; na < 8; na++) {
                uint32_t bb[2];
                bb[0] = vb[(ks * 8 + tq) * FKSTR + na * 8 + g];
                bb[1] = vb[(ks * 8 + tq + 4) * FKSTR + na * 8 + g];
                mma_tf32(oacc[na], pf, bb);
            }
        }
        __syncthreads();                     // all warps done with P & V(it)
        if (it < 7) {
            float* vd = sm + FVOFF + ((it + 1) & 1) * FKSTG;
#pragma unroll
            for (int i = 0; i < 8; i++) {
                int vi = tid + i * 256; int r = vi >> 4; int c = (vi & 15) << 2;
                cp16(&vd[r * FKSTR + c],
                     vz + (size_t)((it + 1) * 128 + r) * 2048 + c);
            }
            cp_commit();
        }
    }

    // ---- epilogue: pad column + noise + write ----
    const int n = z >> 4, h = z & 15;
    float mf0 = fmaxf(m0, 0.f), mf1 = fmaxf(m1, 0.f);
    float sc0 = expf(m0 - mf0), sc1 = expf(m1 - mf1);
    float ep0 = expf(-mf0), ep1 = expf(-mf1);
    float zf0 = z0 * sc0 + ep0, zf1 = z1 * sc1 + ep1;
    float inv0 = 1.f / zf0, inv1 = 1.f / zf1;
    float wp0 = tf32r(ep0 * inv0), wp1 = tf32r(ep1 * inv1);
    float f0 = sc0 * inv0, f1 = sc1 * inv1;
    int l0 = lt * 128 + wr0 + g, l1 = l0 + 8;
    if (tq == 0) {
        msav [z * LLQ + l0] = mf0;  msav [z * LLQ + l1] = mf1;
        zisav[z * LLQ + l0] = inv0; zisav[z * LLQ + l1] = inv1;
    }
    const float* nz = noise + z * 64;
    float* a0 = attn + (size_t)(l0 * 2 + n) * 1024 + h * 64;
    float* a1 = attn + (size_t)(l1 * 2 + n) * 1024 + h * 64;
#pragma unroll
    for (int na = 0; na < 8; na++) {
        int d0 = na * 8 + tq * 2;
        float n0 = tf32r(nz[d0]), n1 = tf32r(nz[d0 + 1]);
        float v00 = tf32r(oacc[na][0] * f0 + wp0 * n0);
        float v01 = tf32r(oacc[na][1] * f0 + wp0 * n1);
        float v10 = tf32r(oacc[na][2] * f1 + wp1 * n0);
        float v11 = tf32r(oacc[na][3] * f1 + wp1 * n1);
        *reinterpret_cast<float2*>(a0 + d0) = make_float2(v00, v01);
        *reinterpret_cast<float2*>(a1 + d0) = make_float2(v10, v11);
    }
}

// ================= attn_map recompute (last layer) =================
// grid (8 s-tiles, 32 l-tiles, 2 n). Recomputes S bitwise-identically,
// w = exp(s-m)*zi, accumulates sigmoid over h.
#define SEG_SMEM (4 * FKSTG * 4)   // 139264 B
__global__ void __launch_bounds__(256, 1)
segmap_kernel(const float* __restrict__ q, const float* __restrict__ k,
              const float* __restrict__ msav, const float* __restrict__ zisav,
              float* __restrict__ outm)
{
    extern __shared__ __align__(16) float sm[];
    const int st = blockIdx.x, lt = blockIdx.y, n = blockIdx.z;
    const int tid = threadIdx.x, wid = tid >> 5, lane = tid & 31;
    const int g = lane >> 2, tq = lane & 3;
    const int ltile = lane >> 3, lr = lane & 7;
    const int wr0 = wid * 16;
    const uint32_t sbase = (uint32_t)__cvta_generic_to_shared(sm);

    auto issue = [&](int h) {
        int z = n * 16 + h, buf = h & 1;
        const float* qz = q + z * 64;
        const float* kz = k + z * 64;
        float* qd = sm + buf * FKSTG;
        float* kd = sm + (2 + buf) * FKSTG;
#pragma unroll
        for (int i = 0; i < 8; i++) {
            int vi = tid + i * 256; int r = vi >> 4; int c = (vi & 15) << 2;
            cp16(&qd[r * FKSTR + c], qz + (size_t)(lt * 128 + r) * 2048 + c);
        }
#pragma unroll
        for (int i = 0; i < 8; i++) {
            int vi = tid + i * 256; int r = vi >> 4; int c = (vi & 15) << 2;
            cp16(&kd[r * FKSTR + c], kz + (size_t)(st * 128 + r) * 2048 + c);
        }
        cp_commit();
    };

    float macc[16][4];
#pragma unroll
    for (int na = 0; na < 16; na++)
#pragma unroll
        for (int e = 0; e < 4; e++) macc[na][e] = 0.f;

    issue(0);
    for (int h = 0; h < 16; h++) {
        cp_wait<0>(); __syncthreads();
        if (h < 15) issue(h + 1);
        const int z = n * 16 + h, buf = h & 1;
        const uint32_t qaddr = sbase +
            (buf * FKSTG + (wr0 + (ltile & 1) * 8 + lr) * FKSTR
             + (ltile >> 1) * 4) * 4;
        const uint32_t kbase = sbase + ((2 + buf) * FKSTG) * 4;

        float sacc[16][4];
#pragma unroll
        for (int na = 0; na < 16; na++)
#pragma unroll
            for (int e = 0; e < 4; e++) sacc[na][e] = 0.f;
#pragma unroll
        for (int ka = 0; ka < 8; ka++) {
            uint32_t qf[4];
            ldsm4(qf[0], qf[1], qf[2], qf[3], qaddr + ka * 32);
            uint32_t kf[16][2];
#pragma unroll
            for (int p = 0; p < 8; p++)
                ldsm4(kf[2 * p][0], kf[2 * p][1], kf[2 * p + 1][0],
                      kf[2 * p + 1][1],
                      kbase + ((p * 16 + (ltile >> 1) * 8 + lr) * FKSTR
                               + (ltile & 1) * 4) * 4 + ka * 32);
#pragma unroll
            for (int na = 0; na < 16; na++)
                mma_tf32(sacc[na], qf, kf[na]);
        }
        int l0 = lt * 128 + wr0 + g;
        float mm0 = msav[z * LLQ + l0],     zi0 = zisav[z * LLQ + l0];
        float mm1 = msav[z * LLQ + l0 + 8], zi1 = zisav[z * LLQ + l0 + 8];
#pragma unroll
        for (int na = 0; na < 16; na++) {
            float w0 = expf(sacc[na][0] - mm0) * zi0;
            float w1 = expf(sacc[na][1] - mm0) * zi0;
            float w2 = expf(sacc[na][2] - mm1) * zi1;
            float w3 = expf(sacc[na][3] - mm1) * zi1;
            macc[na][0] += 1.f / (1.f + expf(-w0));
            macc[na][1] += 1.f / (1.f + expf(-w1));
            macc[na][2] += 1.f / (1.f + expf(-w2));
            macc[na][3] += 1.f / (1.f + expf(-w3));
        }
    }

    size_t base = (size_t)ROWS_T * DDIM + (size_t)n * LLQ * SS;
    int l0 = lt * 128 + wr0 + g;
#pragma unroll
    for (int na = 0; na < 16; na++) {
        int c0 = st * 128 + na * 8 + tq * 2;
        *reinterpret_cast<float2*>(&outm[base + (size_t)l0 * SS + c0]) =
            make_float2(macc[na][0] * (1.f / HH), macc[na][1] * (1.f / HH));
        *reinterpret_cast<float2*>(&outm[base + (size_t)(l0 + 8) * SS + c0]) =
            make_float2(macc[na][2] * (1.f / HH), macc[na][3] * (1.f / HH));
    }
}

// ---------------- layernorm over D=1024; optional tf32-rounded copy ----------------
__global__ void ln_kernel(const float* __restrict__ x, const float* __restrict__ g,
                          const float* __restrict__ b, float* __restrict__ y,
                          float* __restrict__ yr) {
    long long row = blockIdx.x;
    const float4* px = reinterpret_cast<const float4*>(x + row * (long long)DDIM);
    int t = threadIdx.x;
    float4 v = px[t];
    __shared__ float r1[256], r2[256];
    r1[t] = v.x + v.y + v.z + v.w;
    r2[t] = v.x*v.x + v.y*v.y + v.z*v.z + v.w*v.w;
    __syncthreads();
    for (int o = 128; o > 0; o >>= 1) {
        if (t < o) { r1[t] += r1[t + o]; r2[t] += r2[t + o]; }
        __syncthreads();
    }
    float mu  = r1[0] * (1.f / DDIM);
    float var = r2[0] * (1.f / DDIM) - mu * mu;
    float rs  = rsqrtf(var + 1e-5f);
    float4 gg = reinterpret_cast<const float4*>(g)[t];
    float4 bb = reinterpret_cast<const float4*>(b)[t];
    float4 o4;
    o4.x = (v.x - mu) * rs * gg.x + bb.x;
    o4.y = (v.y - mu) * rs * gg.y + bb.y;
    o4.z = (v.z - mu) * rs * gg.z + bb.z;
    o4.w = (v.w - mu) * rs * gg.w + bb.w;
    reinterpret_cast<float4*>(y + row * (long long)DDIM)[t] = o4;
    if (yr) {
        float4 q4;
        q4.x = tf32r(o4.x); q4.y = tf32r(o4.y);
        q4.z = tf32r(o4.z); q4.w = tf32r(o4.w);
        reinterpret_cast<float4*>(yr + row * (long long)DDIM)[t] = q4;
    }
}

// ---------------- host launchers ----------------
static const int SMEM_TB  = 2 * (128 * 36 + 128 * 36) * 4;   // 73728 B

static void gemm_tb(int M, int Nn, int K,
                    const float* A, int lda, long long sA,
                    const float* B, int ldb, long long sB,
                    const float* bias, float alpha,
                    const float* resid, int ldr, int relu, int roundc,
                    float* C, int ldc, long long sC, int batch) {
    cudaFuncSetAttribute(mma_gemm<128, 128, 64, 32, true>,
                         cudaFuncAttributeMaxDynamicSharedMemorySize, SMEM_TB);
    dim3 grid(Nn / 128, M / 128, batch), blk(256);
    mma_gemm<128, 128, 64, 32, true><<<grid, blk, SMEM_TB>>>(
        M, Nn, K, A, lda, sA, B, ldb, sB, bias, alpha, resid, ldr, relu, roundc,
        C, ldc, sC);
}
static void rcopy(const float* in, float* out, long long n) {
    int n4 = (int)(n / 4);
    round_copy<<<(n4 + 255) / 256, 256>>>(
        (const float4*)in, (float4*)out, n4);
}

extern "C" void kernel_launch(void* const* d_in, const int* in_sizes, int n_in,
                              void* d_out, int out_size) {
    const float* key_in    = (const float*)d_in[0];
    const float* value_in  = (const float*)d_in[1];
    const float* query     = (const float*)d_in[2];
    const float* in_proj_w = (const float*)d_in[3];
    const float* in_proj_b = (const float*)d_in[4];
    const float* out_w     = (const float*)d_in[5];
    const float* out_b     = (const float*)d_in[6];
    const float* ln1_g     = (const float*)d_in[7];
    const float* ln1_b     = (const float*)d_in[8];
    const float* ln2_g     = (const float*)d_in[9];
    const float* ln2_b     = (const float*)d_in[10];
    const float* ff1_w     = (const float*)d_in[11];
    const float* ff1_b     = (const float*)d_in[12];
    const float* ff2_w     = (const float*)d_in[13];
    const float* ff2_b     = (const float*)d_in[14];
    float* out = (float*)d_out;

    float *q, *k, *v, *attn, *x1, *x, *hbuf, *y, *tgt, *noise, *msav, *zisav;
    float *ipw, *oww, *f1w, *f2w, *keyr, *valr, *qryr, *xr, *tgtr;
    cudaGetSymbolAddress((void**)&q,     g_q);
    cudaGetSymbolAddress((void**)&k,     g_k);
    cudaGetSymbolAddress((void**)&v,     g_v);
    cudaGetSymbolAddress((void**)&attn,  g_attn);
    cudaGetSymbolAddress((void**)&x1,    g_x1);
    cudaGetSymbolAddress((void**)&x,     g_x);
    cudaGetSymbolAddress((void**)&hbuf,  g_h);
    cudaGetSymbolAddress((void**)&y,     g_y);
    cudaGetSymbolAddress((void**)&tgt,   g_tgt);
    cudaGetSymbolAddress((void**)&noise, g_noise);
    cudaGetSymbolAddress((void**)&msav,  g_m);
    cudaGetSymbolAddress((void**)&zisav, g_zi);
    cudaGetSymbolAddress((void**)&ipw,   g_ipw);
    cudaGetSymbolAddress((void**)&oww,   g_oww);
    cudaGetSymbolAddress((void**)&f1w,   g_f1w);
    cudaGetSymbolAddress((void**)&f2w,   g_f2w);
    cudaGetSymbolAddress((void**)&keyr,  g_keyr);
    cudaGetSymbolAddress((void**)&valr,  g_valr);
    cudaGetSymbolAddress((void**)&qryr,  g_qryr);
    cudaGetSymbolAddress((void**)&xr,    g_xr);
    cudaGetSymbolAddress((void**)&tgtr,  g_tgtr);

    cudaFuncSetAttribute(flash_kernel,
                         cudaFuncAttributeMaxDynamicSharedMemorySize, FL_SMEM);
    cudaFuncSetAttribute(segmap_kernel,
                         cudaFuncAttributeMaxDynamicSharedMemorySize, SEG_SMEM);

    rcopy(in_proj_w, ipw,  (long long)NL * 3 * DDIM * DDIM);
    rcopy(out_w,     oww,  (long long)NL * DDIM * DDIM);
    rcopy(ff1_w,     f1w,  (long long)NL * FFD * DDIM);
    rcopy(ff2_w,     f2w,  (long long)NL * DDIM * FFD);
    rcopy(key_in,    keyr, (long long)ROWS_S * DDIM);
    rcopy(value_in,  valr, (long long)ROWS_S * DDIM);
    rcopy(query,     qryr, (long long)ROWS_T * DDIM);

    noise_kernel<<<(NL * 2048 + 255) / 256, 256>>>(noise);

    for (int i = 0; i < NL; i++) {
        const float* tinr = (i == 0) ? qryr : tgtr;   // rounded (GEMM A)
        const float* tine = (i == 0) ? query : tgt;   // exact (residual)
        const float* W    = ipw + (size_t)i * 3 * DDIM * DDIM;
        const float* Bb   = in_proj_b + (size_t)i * 3 * DDIM;

        gemm_tb(ROWS_T, DDIM, DDIM, tinr, DDIM, 0, W,                 DDIM, 0,
                Bb,            SCALING, nullptr, 0, 0, 1, q, DDIM, 0, 1);
        gemm_tb(ROWS_S, DDIM, DDIM, keyr, DDIM, 0, W +     DDIM*DDIM, DDIM, 0,
                Bb + DDIM,     1.f,     nullptr, 0, 0, 1, k, DDIM, 0, 1);
        gemm_tb(ROWS_S, DDIM, DDIM, valr, DDIM, 0, W + 2 * DDIM*DDIM, DDIM, 0,
                Bb + 2 * DDIM, 1.f,     nullptr, 0, 0, 1, v, DDIM, 0, 1);

        // fused attention: scores + softmax + PV + pad noise, writes attn (tf32)
        {
            dim3 fg(LLQ / 128, NB * HH);
            flash_kernel<<<fg, 256, FL_SMEM>>>(
                q, k, v, noise + (size_t)i * NB * HH * HDIM, attn, msav, zisav);
        }
        if (i == NL - 1) {
            dim3 sg(SS / 128, LLQ / 128, NB);
            segmap_kernel<<<sg, 256, SEG_SMEM>>>(q, k, msav, zisav, out);
        }

        // out-proj + residual -> LN1 (x exact + xr rounded)
        gemm_tb(ROWS_T, DDIM, DDIM, attn, DDIM, 0, oww + (size_t)i * DDIM * DDIM,
                DDIM, 0, out_b + i * DDIM, 1.f, tine, DDIM, 0, 0, x1, DDIM, 0, 1);
        ln_kernel<<<ROWS_T, 256>>>(x1, ln1_g + i * DDIM, ln1_b + i * DDIM, x, xr);

        // FFN
        gemm_tb(ROWS_T, FFD, DDIM, xr, DDIM, 0, f1w + (size_t)i * FFD * DDIM,
                DDIM, 0, ff1_b + i * FFD, 1.f, nullptr, 0, 1, 1, hbuf, FFD, 0, 1);
        gemm_tb(ROWS_T, DDIM, FFD, hbuf, FFD, 0, f2w + (size_t)i * DDIM * FFD,
                FFD, 0, ff2_b + i * DDIM, 1.f, x, DDIM, 0, 0, y, DDIM, 0, 1);

        if (i == NL - 1)
            ln_kernel<<<ROWS_T, 256>>>(y, ln2_g + i * DDIM, ln2_b + i * DDIM,
                                       out, nullptr);
        else
            ln_kernel<<<ROWS_T, 256>>>(y, ln2_g + i * DDIM, ln2_b + i * DDIM,
                                       tgt, tgtr);
    }
}

// round 13
// speedup vs baseline: 3.5147x; 1.0013x over previous
#include <cuda_runtime.h>
#include <cstdint>
#include <math.h>

// ---------------- problem constants ----------------
#define NL   2
#define DDIM 1024
#define HH   16
#define HDIM 64
#define FFD  4096
#define SS   1024
#define NB   2
#define LLQ  4096
#define ROWS_T (LLQ*NB)   // 8192 query rows
#define ROWS_S (SS*NB)    // 2048 kv rows
#define SCALING 0.125f    // HD^-0.5

// ---------------- device scratch (static, allocation-free) ----------------
__device__ float g_q   [ROWS_T*DDIM];
__device__ float g_kv  [2*ROWS_S*DDIM];     // k then v
__device__ float g_attn[ROWS_T*DDIM];
__device__ float g_x1  [ROWS_T*DDIM];
__device__ float g_x   [ROWS_T*DDIM];
__device__ float g_h   [ROWS_T*FFD];
__device__ float g_y   [ROWS_T*DDIM];
__device__ float g_tgt [ROWS_T*DDIM];
__device__ float g_noise[NL*NB*HH*HDIM];
__device__ float g_m   [NB*HH*LLQ];
__device__ float g_zi  [NB*HH*LLQ];
// pre-rounded (tf32) copies
__device__ float g_ipw [NL*3*DDIM*DDIM];
__device__ float g_oww [NL*DDIM*DDIM];
__device__ float g_f1w [NL*FFD*DDIM];
__device__ float g_f2w [NL*DDIM*FFD];
__device__ float g_kvr [2*ROWS_S*DDIM];     // rounded key_in then value_in
__device__ float g_qryr[ROWS_T*DDIM];
__device__ float g_xr  [ROWS_T*DDIM];
__device__ float g_tgtr[ROWS_T*DDIM];

// ---------------- TF32 rounding ----------------
__device__ __forceinline__ float tf32r(float x) {
    asm("cvt.rna.tf32.f32 %0, %0;" : "+f"(x));
    return x;
}

// ---------------- merged pre-rounding (one launch) ----------------
struct RC {
    const float4* s[7];
    float4*       d[7];
    int           n4[7];
};
__global__ void round_all(RC rc) {
    int i = blockIdx.x * blockDim.x + threadIdx.x;
#pragma unroll
    for (int seg = 0; seg < 7; seg++) {
        if (i < rc.n4[seg]) {
            float4 t = rc.s[seg][i];
            t.x = tf32r(t.x); t.y = tf32r(t.y);
            t.z = tf32r(t.z); t.w = tf32r(t.w);
            rc.d[seg][i] = t;
            return;
        }
        i -= rc.n4[seg];
    }
}

// ---------------- cp.async helpers ----------------
__device__ __forceinline__ void cp16(void* s, const void* g) {
    uint32_t sa = (uint32_t)__cvta_generic_to_shared(s);
    asm volatile("cp.async.cg.shared.global [%0], [%1], 16;" :: "r"(sa), "l"(g));
}
__device__ __forceinline__ void cp_commit() {
    asm volatile("cp.async.commit_group;");
}
template<int N>
__device__ __forceinline__ void cp_wait() {
    asm volatile("cp.async.wait_group %0;" :: "n"(N));
}

// ---------------- ldmatrix (tf32 fragments via b16 tiles) ----------------
__device__ __forceinline__ void ldsm4(uint32_t& r0, uint32_t& r1,
                                      uint32_t& r2, uint32_t& r3, uint32_t addr) {
    asm volatile("ldmatrix.sync.aligned.m8n8.x4.shared.b16 {%0,%1,%2,%3}, [%4];"
                 : "=r"(r0), "=r"(r1), "=r"(r2), "=r"(r3) : "r"(addr));
}

// ---------------- JAX threefry2x32 (partitionable) ----------------
__device__ __forceinline__ uint32_t rotl32(uint32_t x, int d) {
    return (x << d) | (x >> (32 - d));
}
__device__ __forceinline__ void threefry2x32(uint32_t k0, uint32_t k1,
                                             uint32_t& x0, uint32_t& x1) {
    uint32_t ks2 = k0 ^ k1 ^ 0x1BD11BDAu;
    x0 += k0; x1 += k1;
#define TFR(r) { x0 += x1; x1 = rotl32(x1, (r)); x1 ^= x0; }
    TFR(13) TFR(15) TFR(26) TFR(6)
    x0 += k1; x1 += ks2 + 1u;
    TFR(17) TFR(29) TFR(16) TFR(24)
    x0 += ks2; x1 += k0 + 2u;
    TFR(13) TFR(15) TFR(26) TFR(6)
    x0 += k0; x1 += k1 + 3u;
    TFR(17) TFR(29) TFR(16) TFR(24)
    x0 += k1; x1 += ks2 + 4u;
    TFR(13) TFR(15) TFR(26) TFR(6)
    x0 += ks2; x1 += k0 + 5u;
#undef TFR
}
__device__ __forceinline__ float bits_to_normal(uint32_t b) {
    float f = __uint_as_float((b >> 9) | 0x3F800000u) - 1.0f;   // [0,1)
    const float lo = -0.99999994f;
    float u = fmaxf(lo, f * 2.0f + lo);
    return 1.4142135623730951f * erfinvf(u);
}
__global__ void noise_kernel(float* __restrict__ noise) {
    int j = blockIdx.x * blockDim.x + threadIdx.x;
    if (j >= NL * 2048) return;
    int layer = j / 2048, jj = j % 2048;
    uint32_t k0 = 0u, k1 = 42u, x0 = 0u, x1 = (uint32_t)layer;
    threefry2x32(k0, k1, x0, x1);
    uint32_t b0 = 0u, b1 = (uint32_t)jj;
    threefry2x32(x0, x1, b0, b1);
    noise[layer * 2048 + jj] = bits_to_normal(b0 ^ b1);
}

// ---------------- TF32 tensor-core GEMM (mma.sync.m16n8k8) ----------------
__device__ __forceinline__ void mma_tf32(float* d, const uint32_t* a, const uint32_t* b) {
    asm volatile(
        "mma.sync.aligned.m16n8k8.row.col.f32.tf32.tf32.f32 "
        "{%0,%1,%2,%3}, {%4,%5,%6,%7}, {%8,%9}, {%0,%1,%2,%3};\n"
        : "+f"(d[0]), "+f"(d[1]), "+f"(d[2]), "+f"(d[3])
        : "r"(a[0]), "r"(a[1]), "r"(a[2]), "r"(a[3]), "r"(b[0]), "r"(b[1]));
}

// ================= generic GEMM: 3-stage cp.async, one sync per k-step ======
template<int BM, int BN, int WM, int WN>
__global__ __launch_bounds__(256, 2)
void mma_gemm(int M, int Nn, int K,
              const float* __restrict__ A, int lda, long long sA,
              const float* __restrict__ B, int ldb, long long sB,
              const float* __restrict__ bias, int bstride, float alpha,
              const float* __restrict__ resid, int ldr, int relu, int roundc,
              float* __restrict__ C, int ldc, long long sC)
{
    constexpr int BK = 32;
    constexpr int STG = 3;
    constexpr int SA  = BK + 4;                   // 36
    constexpr int ASTG = BM * SA;
    constexpr int BSTG = BN * SA;

    extern __shared__ __align__(16) float smem[];
    float* As = smem;
    float* Bs = smem + STG * ASTG;

    long long bz = blockIdx.z;
    A += bz * sA; B += bz * sB; C += bz * sC;
    if (bias) bias += bz * bstride;
    const int bm = blockIdx.y * BM;
    const int bn = blockIdx.x * BN;
    const int tid = threadIdx.x;
    const int wid = tid >> 5, lane = tid & 31;
    const int g = lane >> 2, tq = lane & 3;
    constexpr int WX = BN / WN;
    const int wm = (wid / WX) * WM, wn = (wid % WX) * WN;
    constexpr int MA = WM / 16, NA = WN / 8;

    float acc[MA][NA][4];
#pragma unroll
    for (int i = 0; i < MA; i++)
#pragma unroll
        for (int j = 0; j < NA; j++)
#pragma unroll
            for (int e = 0; e < 4; e++) acc[i][j][e] = 0.f;

    const int ltile = lane >> 3, lr = lane & 7;
    const uint32_t s_base = (uint32_t)__cvta_generic_to_shared(smem);
    uint32_t baseA[MA];
#pragma unroll
    for (int ma = 0; ma < MA; ma++)
        baseA[ma] = ((wm + ma * 16 + (ltile & 1) * 8 + lr) * SA
                     + (ltile >> 1) * 4) * 4;
    uint32_t baseB[(NA + 1) / 2];
#pragma unroll
    for (int p = 0; p < NA / 2; p++)
        baseB[p] = ((wn + p * 16 + (ltile >> 1) * 8 + lr) * SA
                    + (ltile & 1) * 4) * 4;

    auto load_tiles = [&](int st, int k0) {
        float* as = As + st * ASTG;
        float* bs = Bs + st * BSTG;
#pragma unroll
        for (int it = 0; it < BM * BK / (4 * 256); it++) {
            int vi = tid + it * 256;
            int r  = vi >> 3;
            int kc = (vi & 7) * 4;
            cp16(&as[r * SA + kc], A + (long long)(bm + r) * lda + k0 + kc);
        }
#pragma unroll
        for (int it = 0; it < BN * BK / (4 * 256); it++) {
            int vi = tid + it * 256;
            int r  = vi >> 3;
            int kc = (vi & 7) * 4;
            cp16(&bs[r * SA + kc], B + (long long)(bn + r) * ldb + k0 + kc);
        }
    };

    const int nk = K / BK;
    load_tiles(0, 0);      cp_commit();
    load_tiles(1, BK);     cp_commit();

    for (int i = 0; i < nk; i++) {
        if (i == nk - 1) { cp_wait<0>(); } else { cp_wait<1>(); }
        __syncthreads();   // stage i published; stage (i-1) consumers all done
        if (i + 2 < nk) {  // refill buffer (i-1)%3 with stage i+2
            load_tiles((i + 2) % STG, (i + 2) * BK);
            cp_commit();
        }

        const int buf = i % STG;
        const uint32_t s_as = s_base + buf * ASTG * 4;
        const uint32_t s_bs = s_base + (STG * ASTG + buf * BSTG) * 4;

#pragma unroll
        for (int ka = 0; ka < BK / 8; ka++) {
            const int kb = ka * 8;
            uint32_t af[MA][4];
            uint32_t bf[NA][2];
#pragma unroll
            for (int ma = 0; ma < MA; ma++)
                ldsm4(af[ma][0], af[ma][1], af[ma][2], af[ma][3],
                      s_as + baseA[ma] + kb * 4);
#pragma unroll
            for (int p = 0; p < NA / 2; p++)
                ldsm4(bf[2 * p][0], bf[2 * p][1], bf[2 * p + 1][0],
                      bf[2 * p + 1][1], s_bs + baseB[p] + kb * 4);
#pragma unroll
            for (int ma = 0; ma < MA; ma++)
#pragma unroll
                for (int na = 0; na < NA; na++)
                    mma_tf32(acc[ma][na], af[ma], bf[na]);
        }
    }

#pragma unroll
    for (int ma = 0; ma < MA; ma++) {
#pragma unroll
        for (int na = 0; na < NA; na++) {
            int c0 = bn + wn + na * 8 + tq * 2;
#pragma unroll
            for (int hh = 0; hh < 2; hh++) {
                long long rr = bm + wm + ma * 16 + g + hh * 8;
                float v0 = acc[ma][na][hh * 2 + 0];
                float v1 = acc[ma][na][hh * 2 + 1];
                if (bias) { v0 += bias[c0]; v1 += bias[c0 + 1]; }
                v0 *= alpha; v1 *= alpha;
                if (resid) {
                    float2 rv = *reinterpret_cast<const float2*>(
                        resid + rr * (long long)ldr + c0);
                    v0 += rv.x; v1 += rv.y;
                }
                if (relu) { v0 = fmaxf(v0, 0.f); v1 = fmaxf(v1, 0.f); }
                if (roundc) { v0 = tf32r(v0); v1 = tf32r(v1); }
                *reinterpret_cast<float2*>(C + rr * (long long)ldc + c0) =
                    make_float2(v0, v1);
            }
        }
    }
}

// ================= fused flash attention (unchanged) =================
#define FKSTR 68
#define FPSTR 132
#define FKSTG (128*FKSTR)
#define FVOFF (2*FKSTG)
#define FPOFF (4*FKSTG)
#define FL_SMEM ((4*FKSTG + 128*FPSTR) * 4)   // 206848 B

__global__ void __launch_bounds__(256, 1)
flash_kernel(const float* __restrict__ q, const float* __restrict__ k,
             const float* __restrict__ v, const float* __restrict__ noise,
             float* __restrict__ attn, float* __restrict__ msav,
             float* __restrict__ zisav)
{
    extern __shared__ __align__(16) float sm[];
    const int z = blockIdx.y, lt = blockIdx.x;
    const int tid = threadIdx.x, wid = tid >> 5, lane = tid & 31;
    const int g = lane >> 2, tq = lane & 3;
    const int ltile = lane >> 3, lr = lane & 7;
    const int wr0 = wid * 16;
    const float* qz = q + z * 64;
    const float* kz = k + z * 64;
    const float* vz = v + z * 64;
    const uint32_t sbase = (uint32_t)__cvta_generic_to_shared(sm);

#pragma unroll
    for (int i = 0; i < 8; i++) {
        int vi = tid + i * 256; int r = vi >> 4; int c = (vi & 15) << 2;
        cp16(&sm[FPOFF + r * FKSTR + c], qz + (size_t)(lt * 128 + r) * 2048 + c);
    }
    cp_commit();
#pragma unroll
    for (int i = 0; i < 8; i++) {
        int vi = tid + i * 256; int r = vi >> 4; int c = (vi & 15) << 2;
        cp16(&sm[r * FKSTR + c], kz + (size_t)r * 2048 + c);
    }
    cp_commit();
#pragma unroll
    for (int i = 0; i < 8; i++) {
        int vi = tid + i * 256; int r = vi >> 4; int c = (vi & 15) << 2;
        cp16(&sm[FVOFF + r * FKSTR + c], vz + (size_t)r * 2048 + c);
    }
    cp_commit();

    cp_wait<2>(); __syncthreads();
    uint32_t qf[8][4];
    {
        uint32_t qaddr = sbase +
            (FPOFF + (wr0 + (ltile & 1) * 8 + lr) * FKSTR + (ltile >> 1) * 4) * 4;
#pragma unroll
        for (int ka = 0; ka < 8; ka++)
            ldsm4(qf[ka][0], qf[ka][1], qf[ka][2], qf[ka][3], qaddr + ka * 32);
    }
    __syncthreads();

    uint32_t kaddr[8];
#pragma unroll
    for (int p = 0; p < 8; p++)
        kaddr[p] = sbase + ((p * 16 + (ltile >> 1) * 8 + lr) * FKSTR
                            + (ltile & 1) * 4) * 4;
    const uint32_t paddr = sbase +
        (FPOFF + (wr0 + (ltile & 1) * 8 + lr) * FPSTR + (ltile >> 1) * 4) * 4;

    float m0 = -1e30f, m1 = -1e30f, z0 = 0.f, z1 = 0.f;
    float oacc[8][4];
#pragma unroll
    for (int na = 0; na < 8; na++)
#pragma unroll
        for (int e = 0; e < 4; e++) oacc[na][e] = 0.f;

    for (int it = 0; it < 8; it++) {
        const int buf = it & 1;
        cp_wait<1>(); __syncthreads();

        float sacc[16][4];
#pragma unroll
        for (int na = 0; na < 16; na++)
#pragma unroll
            for (int e = 0; e < 4; e++) sacc[na][e] = 0.f;
        const uint32_t kboff = (uint32_t)buf * FKSTG * 4;
#pragma unroll
        for (int ka = 0; ka < 8; ka++) {
            uint32_t kf[16][2];
#pragma unroll
            for (int p = 0; p < 8; p++)
                ldsm4(kf[2 * p][0], kf[2 * p][1], kf[2 * p + 1][0],
                      kf[2 * p + 1][1], kaddr[p] + kboff + ka * 32);
#pragma unroll
            for (int na = 0; na < 16; na++)
                mma_tf32(sacc[na], qf[ka], kf[na]);
        }

        if (it < 7) {
            float* kd = sm + ((it + 1) & 1) * FKSTG;
#pragma unroll
            for (int i = 0; i < 8; i++) {
                int vi = tid + i * 256; int r = vi >> 4; int c = (vi & 15) << 2;
                cp16(&kd[r * FKSTR + c],
                     kz + (size_t)((it + 1) * 128 + r) * 2048 + c);
            }
            cp_commit();
        }

        float t0 = -1e30f, t1 = -1e30f;
#pragma unroll
        for (int na = 0; na < 16; na++) {
            t0 = fmaxf(t0, fmaxf(sacc[na][0], sacc[na][1]));
            t1 = fmaxf(t1, fmaxf(sacc[na][2], sacc[na][3]));
        }
        t0 = fmaxf(t0, __shfl_xor_sync(0xffffffffu, t0, 1));
        t0 = fmaxf(t0, __shfl_xor_sync(0xffffffffu, t0, 2));
        t1 = fmaxf(t1, __shfl_xor_sync(0xffffffffu, t1, 1));
        t1 = fmaxf(t1, __shfl_xor_sync(0xffffffffu, t1, 2));
        float mn0 = fmaxf(m0, t0), mn1 = fmaxf(m1, t1);
        float sc0 = expf(m0 - mn0), sc1 = expf(m1 - mn1);
        m0 = mn0; m1 = mn1;
        z0 *= sc0; z1 *= sc1;
#pragma unroll
        for (int na = 0; na < 8; na++) {
            oacc[na][0] *= sc0; oacc[na][1] *= sc0;
            oacc[na][2] *= sc1; oacc[na][3] *= sc1;
        }
        float s0 = 0.f, s1 = 0.f;
#pragma unroll
        for (int na = 0; na < 16; na++) {
            float p0 = expf(sacc[na][0] - mn0), p1 = expf(sacc[na][1] - mn0);
            float p2 = expf(sacc[na][2] - mn1), p3 = expf(sacc[na][3] - mn1);
            s0 += p0 + p1; s1 += p2 + p3;
            int c0 = na * 8 + tq * 2;
            *reinterpret_cast<float2*>(&sm[FPOFF + (wr0 + g) * FPSTR + c0]) =
                make_float2(tf32r(p0), tf32r(p1));
            *reinterpret_cast<float2*>(&sm[FPOFF + (wr0 + g + 8) * FPSTR + c0]) =
                make_float2(tf32r(p2), tf32r(p3));
        }
        s0 += __shfl_xor_sync(0xffffffffu, s0, 1);
        s0 += __shfl_xor_sync(0xffffffffu, s0, 2);
        s1 += __shfl_xor_sync(0xffffffffu, s1, 1);
        s1 += __shfl_xor_sync(0xffffffffu, s1, 2);
        z0 += s0; z1 += s1;

        if (it < 7) { cp_wait<1>(); } else { cp_wait<0>(); }
        __syncthreads();

        const uint32_t* vb =
            reinterpret_cast<const uint32_t*>(sm + FVOFF + buf * FKSTG);
#pragma unroll
        for (int ks = 0; ks < 16; ks++) {
            uint32_t pf[4];
            ldsm4(pf[0], pf[1], pf[2], pf[3], paddr + ks * 32);
#pragma unroll
            for (int na = 0; na < 8; na++) {
                uint32_t bb[2];
                bb[0] = vb[(ks * 8 + tq) * FKSTR + na * 8 + g];
                bb[1] = vb[(ks * 8 + tq + 4) * FKSTR + na * 8 + g];
                mma_tf32(oacc[na], pf, bb);
            }
        }
        __syncthreads();
        if (it < 7) {
            float* vd = sm + FVOFF + ((it + 1) & 1) * FKSTG;
#pragma unroll
            for (int i = 0; i < 8; i++) {
                int vi = tid + i * 256; int r = vi >> 4; int c = (vi & 15) << 2;
                cp16(&vd[r * FKSTR + c],
                     vz + (size_t)((it + 1) * 128 + r) * 2048 + c);
            }
            cp_commit();
        }
    }

    const int n = z >> 4, h = z & 15;
    float mf0 = fmaxf(m0, 0.f), mf1 = fmaxf(m1, 0.f);
    float sc0 = expf(m0 - mf0), sc1 = expf(m1 - mf1);
    float ep0 = expf(-mf0), ep1 = expf(-mf1);
    float zf0 = z0 * sc0 + ep0, zf1 = z1 * sc1 + ep1;
    float inv0 = 1.f / zf0, inv1 = 1.f / zf1;
    float wp0 = tf32r(ep0 * inv0), wp1 = tf32r(ep1 * inv1);
    float f0 = sc0 * inv0, f1 = sc1 * inv1;
    int l0 = lt * 128 + wr0 + g, l1 = l0 + 8;
    if (tq == 0) {
        msav [z * LLQ + l0] = mf0;  msav [z * LLQ + l1] = mf1;
        zisav[z * LLQ + l0] = inv0; zisav[z * LLQ + l1] = inv1;
    }
    const float* nz = noise + z * 64;
    float* a0 = attn + (size_t)(l0 * 2 + n) * 1024 + h * 64;
    float* a1 = attn + (size_t)(l1 * 2 + n) * 1024 + h * 64;
#pragma unroll
    for (int na = 0; na < 8; na++) {
        int d0 = na * 8 + tq * 2;
        float n0 = tf32r(nz[d0]), n1 = tf32r(nz[d0 + 1]);
        float v00 = tf32r(oacc[na][0] * f0 + wp0 * n0);
        float v01 = tf32r(oacc[na][1] * f0 + wp0 * n1);
        float v10 = tf32r(oacc[na][2] * f1 + wp1 * n0);
        float v11 = tf32r(oacc[na][3] * f1 + wp1 * n1);
        *reinterpret_cast<float2*>(a0 + d0) = make_float2(v00, v01);
        *reinterpret_cast<float2*>(a1 + d0) = make_float2(v10, v11);
    }
}

// ================= attn_map recompute (last layer, unchanged) =================
#define SEG_SMEM (4 * FKSTG * 4)   // 139264 B
__global__ void __launch_bounds__(256, 1)
segmap_kernel(const float* __restrict__ q, const float* __restrict__ k,
              const float* __restrict__ msav, const float* __restrict__ zisav,
              float* __restrict__ outm)
{
    extern __shared__ __align__(16) float sm[];
    const int st = blockIdx.x, lt = blockIdx.y, n = blockIdx.z;
    const int tid = threadIdx.x, wid = tid >> 5, lane = tid & 31;
    const int g = lane >> 2, tq = lane & 3;
    const int ltile = lane >> 3, lr = lane & 7;
    const int wr0 = wid * 16;
    const uint32_t sbase = (uint32_t)__cvta_generic_to_shared(sm);

    auto issue = [&](int h) {
        int z = n * 16 + h, buf = h & 1;
        const float* qz = q + z * 64;
        const float* kz = k + z * 64;
        float* qd = sm + buf * FKSTG;
        float* kd = sm + (2 + buf) * FKSTG;
#pragma unroll
        for (int i = 0; i < 8; i++) {
            int vi = tid + i * 256; int r = vi >> 4; int c = (vi & 15) << 2;
            cp16(&qd[r * FKSTR + c], qz + (size_t)(lt * 128 + r) * 2048 + c);
        }
#pragma unroll
        for (int i = 0; i < 8; i++) {
            int vi = tid + i * 256; int r = vi >> 4; int c = (vi & 15) << 2;
            cp16(&kd[r * FKSTR + c], kz + (size_t)(st * 128 + r) * 2048 + c);
        }
        cp_commit();
    };

    float macc[16][4];
#pragma unroll
    for (int na = 0; na < 16; na++)
#pragma unroll
        for (int e = 0; e < 4; e++) macc[na][e] = 0.f;

    issue(0);
    for (int h = 0; h < 16; h++) {
        cp_wait<0>(); __syncthreads();
        if (h < 15) issue(h + 1);
        const int z = n * 16 + h, buf = h & 1;
        const uint32_t qaddr = sbase +
            (buf * FKSTG + (wr0 + (ltile & 1) * 8 + lr) * FKSTR
             + (ltile >> 1) * 4) * 4;
        const uint32_t kbase = sbase + ((2 + buf) * FKSTG) * 4;

        float sacc[16][4];
#pragma unroll
        for (int na = 0; na < 16; na++)
#pragma unroll
            for (int e = 0; e < 4; e++) sacc[na][e] = 0.f;
#pragma unroll
        for (int ka = 0; ka < 8; ka++) {
            uint32_t qf[4];
            ldsm4(qf[0], qf[1], qf[2], qf[3], qaddr + ka * 32);
            uint32_t kf[16][2];
#pragma unroll
            for (int p = 0; p < 8; p++)
                ldsm4(kf[2 * p][0], kf[2 * p][1], kf[2 * p + 1][0],
                      kf[2 * p + 1][1],
                      kbase + ((p * 16 + (ltile >> 1) * 8 + lr) * FKSTR
                               + (ltile & 1) * 4) * 4 + ka * 32);
#pragma unroll
            for (int na = 0; na < 16; na++)
                mma_tf32(sacc[na], qf, kf[na]);
        }
        int l0 = lt * 128 + wr0 + g;
        float mm0 = msav[z * LLQ + l0],     zi0 = zisav[z * LLQ + l0];
        float mm1 = msav[z * LLQ + l0 + 8], zi1 = zisav[z * LLQ + l0 + 8];
#pragma unroll
        for (int na = 0; na < 16; na++) {
            float w0 = expf(sacc[na][0] - mm0) * zi0;
            float w1 = expf(sacc[na][1] - mm0) * zi0;
            float w2 = expf(sacc[na][2] - mm1) * zi1;
            float w3 = expf(sacc[na][3] - mm1) * zi1;
            macc[na][0] += 1.f / (1.f + expf(-w0));
            macc[na][1] += 1.f / (1.f + expf(-w1));
            macc[na][2] += 1.f / (1.f + expf(-w2));
            macc[na][3] += 1.f / (1.f + expf(-w3));
        }
    }

    size_t base = (size_t)ROWS_T * DDIM + (size_t)n * LLQ * SS;
    int l0 = lt * 128 + wr0 + g;
#pragma unroll
    for (int na = 0; na < 16; na++) {
        int c0 = st * 128 + na * 8 + tq * 2;
        *reinterpret_cast<float2*>(&outm[base + (size_t)l0 * SS + c0]) =
            make_float2(macc[na][0] * (1.f / HH), macc[na][1] * (1.f / HH));
        *reinterpret_cast<float2*>(&outm[base + (size_t)(l0 + 8) * SS + c0]) =
            make_float2(macc[na][2] * (1.f / HH), macc[na][3] * (1.f / HH));
    }
}

// ---------------- layernorm over D=1024; optional tf32-rounded copy ----------------
__global__ void ln_kernel(const float* __restrict__ x, const float* __restrict__ g,
                          const float* __restrict__ b, float* __restrict__ y,
                          float* __restrict__ yr) {
    long long row = blockIdx.x;
    const float4* px = reinterpret_cast<const float4*>(x + row * (long long)DDIM);
    int t = threadIdx.x;
    float4 v = px[t];
    __shared__ float r1[256], r2[256];
    r1[t] = v.x + v.y + v.z + v.w;
    r2[t] = v.x*v.x + v.y*v.y + v.z*v.z + v.w*v.w;
    __syncthreads();
    for (int o = 128; o > 0; o >>= 1) {
        if (t < o) { r1[t] += r1[t + o]; r2[t] += r2[t + o]; }
        __syncthreads();
    }
    float mu  = r1[0] * (1.f / DDIM);
    float var = r2[0] * (1.f / DDIM) - mu * mu;
    float rs  = rsqrtf(var + 1e-5f);
    float4 gg = reinterpret_cast<const float4*>(g)[t];
    float4 bb = reinterpret_cast<const float4*>(b)[t];
    float4 o4;
    o4.x = (v.x - mu) * rs * gg.x + bb.x;
    o4.y = (v.y - mu) * rs * gg.y + bb.y;
    o4.z = (v.z - mu) * rs * gg.z + bb.z;
    o4.w = (v.w - mu) * rs * gg.w + bb.w;
    reinterpret_cast<float4*>(y + row * (long long)DDIM)[t] = o4;
    if (yr) {
        float4 q4;
        q4.x = tf32r(o4.x); q4.y = tf32r(o4.y);
        q4.z = tf32r(o4.z); q4.w = tf32r(o4.w);
        reinterpret_cast<float4*>(yr + row * (long long)DDIM)[t] = q4;
    }
}

// ---------------- host launchers ----------------
static const int SMEM_TB = 3 * (128 * 36 + 128 * 36) * 4;   // 110592 B

static void gemm_tb(int M, int Nn, int K,
                    const float* A, int lda, long long sA,
                    const float* B, int ldb, long long sB,
                    const float* bias, int bstride, float alpha,
                    const float* resid, int ldr, int relu, int roundc,
                    float* C, int ldc, long long sC, int batch) {
    cudaFuncSetAttribute(mma_gemm<128, 128, 64, 32>,
                         cudaFuncAttributeMaxDynamicSharedMemorySize, SMEM_TB);
    dim3 grid(Nn / 128, M / 128, batch), blk(256);
    mma_gemm<128, 128, 64, 32><<<grid, blk, SMEM_TB>>>(
        M, Nn, K, A, lda, sA, B, ldb, sB, bias, bstride, alpha,
        resid, ldr, relu, roundc, C, ldc, sC);
}

extern "C" void kernel_launch(void* const* d_in, const int* in_sizes, int n_in,
                              void* d_out, int out_size) {
    const float* key_in    = (const float*)d_in[0];
    const float* value_in  = (const float*)d_in[1];
    const float* query     = (const float*)d_in[2];
    const float* in_proj_w = (const float*)d_in[3];
    const float* in_proj_b = (const float*)d_in[4];
    const float* out_w     = (const float*)d_in[5];
    const float* out_b     = (const float*)d_in[6];
    const float* ln1_g     = (const float*)d_in[7];
    const float* ln1_b     = (const float*)d_in[8];
    const float* ln2_g     = (const float*)d_in[9];
    const float* ln2_b     = (const float*)d_in[10];
    const float* ff1_w     = (const float*)d_in[11];
    const float* ff1_b     = (const float*)d_in[12];
    const float* ff2_w     = (const float*)d_in[13];
    const float* ff2_b     = (const float*)d_in[14];
    float* out = (float*)d_out;

    float *q, *kv, *attn, *x1, *x, *hbuf, *y, *tgt, *noise, *msav, *zisav;
    float *ipw, *oww, *f1w, *f2w, *kvr, *qryr, *xr, *tgtr;
    cudaGetSymbolAddress((void**)&q,     g_q);
    cudaGetSymbolAddress((void**)&kv,    g_kv);
    cudaGetSymbolAddress((void**)&attn,  g_attn);
    cudaGetSymbolAddress((void**)&x1,    g_x1);
    cudaGetSymbolAddress((void**)&x,     g_x);
    cudaGetSymbolAddress((void**)&hbuf,  g_h);
    cudaGetSymbolAddress((void**)&y,     g_y);
    cudaGetSymbolAddress((void**)&tgt,   g_tgt);
    cudaGetSymbolAddress((void**)&noise, g_noise);
    cudaGetSymbolAddress((void**)&msav,  g_m);
    cudaGetSymbolAddress((void**)&zisav, g_zi);
    cudaGetSymbolAddress((void**)&ipw,   g_ipw);
    cudaGetSymbolAddress((void**)&oww,   g_oww);
    cudaGetSymbolAddress((void**)&f1w,   g_f1w);
    cudaGetSymbolAddress((void**)&f2w,   g_f2w);
    cudaGetSymbolAddress((void**)&kvr,   g_kvr);
    cudaGetSymbolAddress((void**)&qryr,  g_qryr);
    cudaGetSymbolAddress((void**)&xr,    g_xr);
    cudaGetSymbolAddress((void**)&tgtr,  g_tgtr);

    float* kbuf = kv;
    float* vbuf = kv + (size_t)ROWS_S * DDIM;

    cudaFuncSetAttribute(flash_kernel,
                         cudaFuncAttributeMaxDynamicSharedMemorySize, FL_SMEM);
    cudaFuncSetAttribute(segmap_kernel,
                         cudaFuncAttributeMaxDynamicSharedMemorySize, SEG_SMEM);

    // single merged pre-rounding launch
    {
        RC rc;
        const float* srcs[7] = {in_proj_w, out_w, ff1_w, ff2_w,
                                key_in, value_in, query};
        float* dsts[7] = {ipw, oww, f1w, f2w,
                          kvr, kvr + (size_t)ROWS_S * DDIM, qryr};
        long long ns[7] = {(long long)NL*3*DDIM*DDIM, (long long)NL*DDIM*DDIM,
                           (long long)NL*FFD*DDIM, (long long)NL*DDIM*FFD,
                           (long long)ROWS_S*DDIM, (long long)ROWS_S*DDIM,
                           (long long)ROWS_T*DDIM};
        long long tot4 = 0;
        for (int s = 0; s < 7; s++) {
            rc.s[s] = (const float4*)srcs[s];
            rc.d[s] = (float4*)dsts[s];
            rc.n4[s] = (int)(ns[s] / 4);
            tot4 += rc.n4[s];
        }
        round_all<<<(int)((tot4 + 255) / 256), 256>>>(rc);
    }
    noise_kernel<<<(NL * 2048 + 255) / 256, 256>>>(noise);

    for (int i = 0; i < NL; i++) {
        const float* tinr = (i == 0) ? qryr : tgtr;
        const float* tine = (i == 0) ? query : tgt;
        const float* W    = ipw + (size_t)i * 3 * DDIM * DDIM;
        const float* Bb   = in_proj_b + (size_t)i * 3 * DDIM;

        // q projection
        gemm_tb(ROWS_T, DDIM, DDIM, tinr, DDIM, 0, W, DDIM, 0,
                Bb, 0, SCALING, nullptr, 0, 0, 1, q, DDIM, 0, 1);
        // k & v projections batched (z=2)
        gemm_tb(ROWS_S, DDIM, DDIM,
                kvr, DDIM, (long long)ROWS_S * DDIM,
                W + DDIM * DDIM, DDIM, (long long)DDIM * DDIM,
                Bb + DDIM, DDIM, 1.f, nullptr, 0, 0, 1,
                kv, DDIM, (long long)ROWS_S * DDIM, 2);

        // fused attention
        {
            dim3 fg(LLQ / 128, NB * HH);
            flash_kernel<<<fg, 256, FL_SMEM>>>(
                q, kbuf, vbuf, noise + (size_t)i * NB * HH * HDIM,
                attn, msav, zisav);
        }
        if (i == NL - 1) {
            dim3 sg(SS / 128, LLQ / 128, NB);
            segmap_kernel<<<sg, 256, SEG_SMEM>>>(q, kbuf, msav, zisav, out);
        }

        // out-proj + residual -> LN1
        gemm_tb(ROWS_T, DDIM, DDIM, attn, DDIM, 0, oww + (size_t)i * DDIM * DDIM,
                DDIM, 0, out_b + i * DDIM, 0, 1.f, tine, DDIM, 0, 0,
                x1, DDIM, 0, 1);
        ln_kernel<<<ROWS_T, 256>>>(x1, ln1_g + i * DDIM, ln1_b + i * DDIM, x, xr);

        // FFN
        gemm_tb(ROWS_T, FFD, DDIM, xr, DDIM, 0, f1w + (size_t)i * FFD * DDIM,
                DDIM, 0, ff1_b + i * FFD, 0, 1.f, nullptr, 0, 1, 1,
                hbuf, FFD, 0, 1);
        gemm_tb(ROWS_T, DDIM, FFD, hbuf, FFD, 0, f2w + (size_t)i * DDIM * FFD,
                FFD, 0, ff2_b + i * DDIM, 0, 1.f, x, DDIM, 0, 0,
                y, DDIM, 0, 1);

        if (i == NL - 1)
            ln_kernel<<<ROWS_T, 256>>>(y, ln2_g + i * DDIM, ln2_b + i * DDIM,
                                       out, nullptr);
        else
            ln_kernel<<<ROWS_T, 256>>>(y, ln2_g + i * DDIM, ln2_b + i * DDIM,
                                       tgt, tgtr);
    }
}